// round 7
// baseline (speedup 1.0000x reference)
#include <cuda_runtime.h>
#include <cuda_bf16.h>
#include <math.h>
#include <stdint.h>

#define BATCH 4
#define SEQ   512
#define DM    1024
#define NH    16
#define NL    8
#define VOCAB 32000
#define HDIM  64
#define DFF   4096
#define MROWS (BATCH*SEQ)

__device__ float g_x [MROWS*DM];
__device__ float g_t0[MROWS*DM];
__device__ float g_t1[MROWS*DM];
__device__ float g_t2[MROWS*DM];
__device__ float g_t3[MROWS*DM];
__device__ float g_f1[MROWS*DFF];

__global__ void embed_kernel(const int* __restrict__ tokens,
                             const float* __restrict__ emb,
                             const float* __restrict__ pe,
                             float* __restrict__ x)
{
    int idx = blockIdx.x * blockDim.x + threadIdx.x;
    if (idx >= MROWS * DM) return;
    int d  = idx % DM;
    int nt = idx / DM;
    int n  = nt / SEQ;
    int tok = tokens[nt];
    x[idx] = emb[(size_t)tok * DM + d] + pe[(size_t)n * DM + d];
}

// ===================== tf32 mma.sync GEMM (pipelined, ldmatrix A+B) ==========
// C(MxN)=A(MxK)@B(KxN)+bias (opt ReLU). Tile 128x64, BK=32, 2-stage smem ring.
// 256 thr (8 warps 4x2), warp tile 32x32.
// A row-major smem [128][36]; B transposed to n-major smem [64][36].
// All fragments via ldmatrix.m8n8.x4.b16 (pattern == tf32 m16n8k8 frags).
#define PADK 36
#define A_FL (128*PADK)          // 4608 floats
#define B_FL (64*PADK)           // 2304 floats
#define STG_FL (A_FL + B_FL)     // 6912 floats
#define STG_BYTES (STG_FL*4)     // 27648
#define GEMM_SMEM (2*STG_BYTES)  // 55296

__device__ __forceinline__ uint32_t cvta_smem(const void* p){
    uint32_t a;
    asm("{ .reg .u64 t; cvta.to.shared.u64 t, %1; cvt.u32.u64 %0, t; }" : "=r"(a) : "l"(p));
    return a;
}
__device__ __forceinline__ float to_tf32(float x){
    uint32_t u;
    asm("cvt.rna.tf32.f32 %0, %1;" : "=r"(u) : "f"(x));
    return __uint_as_float(u);
}
__device__ __forceinline__ void ldm4(uint32_t* r, uint32_t addr){
    asm volatile("ldmatrix.sync.aligned.m8n8.x4.shared.b16 {%0,%1,%2,%3}, [%4];"
                 : "=r"(r[0]), "=r"(r[1]), "=r"(r[2]), "=r"(r[3]) : "r"(addr));
}
__device__ __forceinline__ void mma_tf32(float* c, const uint32_t* a, const uint32_t* b){
    asm volatile(
        "mma.sync.aligned.m16n8k8.row.col.f32.tf32.tf32.f32 "
        "{%0,%1,%2,%3}, {%4,%5,%6,%7}, {%8,%9}, {%0,%1,%2,%3};"
        : "+f"(c[0]), "+f"(c[1]), "+f"(c[2]), "+f"(c[3])
        : "r"(a[0]), "r"(a[1]), "r"(a[2]), "r"(a[3]), "r"(b[0]), "r"(b[1]));
}

template<bool RELU>
__global__ void __launch_bounds__(256, 2)
tf32_gemm(const float* __restrict__ A, const float* __restrict__ B,
          const float* __restrict__ bias, float* __restrict__ C,
          int Nn, int K)
{
    extern __shared__ float smem[];
    const int tid = threadIdx.x, lane = tid & 31, warp = tid >> 5;
    const int warp_m = warp & 3, warp_n = warp >> 2;
    const int mbase = blockIdx.x * 128, nbase = blockIdx.y * 64;

    const float* Ag = A + (size_t)mbase * K;
    const float* Bg = B + nbase;
    const int NC = K >> 5;

    // global load mappings
    const int arow = tid >> 3, ak4 = (tid & 7) << 2;   // A: 4 rows (32 apart), 4 floats
    const int r = tid & 3, q = tid >> 2;               // B quad transpose mapping
    const int kq = q >> 3, nq8 = q & 7;                // k-group 0..7, n-group 0..7 (+8p)

    // fragment mappings (precomputed byte offsets within a stage)
    const int g = lane >> 2, tig = lane & 3;
    const int sel = lane >> 3, l7 = lane & 7;
    const uint32_t smem_u = cvta_smem(smem);
    uint32_t a_rel[2], b_rel[2];
#pragma unroll
    for (int mt = 0; mt < 2; mt++){
        int row = warp_m * 32 + mt * 16 + (sel & 1) * 8 + l7;
        int col = (sel >> 1) * 4;
        a_rel[mt] = (uint32_t)(row * PADK + col) * 4u;
    }
#pragma unroll
    for (int np = 0; np < 2; np++){
        int nrow = warp_n * 32 + np * 16 + (sel >> 1) * 8 + l7;
        int col  = (sel & 1) * 4;
        b_rel[np] = (uint32_t)(A_FL + nrow * PADK + col) * 4u;
    }

    float acc[2][4][4];
#pragma unroll
    for (int mt = 0; mt < 2; mt++)
#pragma unroll
        for (int np = 0; np < 4; np++)
#pragma unroll
            for (int i = 0; i < 4; i++) acc[mt][np][i] = 0.f;

    float4 ra[4]; float4 rb[2];

    // helper lambdas (inlined): store chunk into stage
    auto store_stage = [&](int stage){
        float* As_ = smem + stage * STG_FL;
        float* Bs_ = As_ + A_FL;
#pragma unroll
        for (int p = 0; p < 4; p++){
            float4 v = ra[p];
            v.x = to_tf32(v.x); v.y = to_tf32(v.y); v.z = to_tf32(v.z); v.w = to_tf32(v.w);
            *(float4*)&As_[(32*p + arow) * PADK + ak4] = v;
        }
#pragma unroll
        for (int p = 0; p < 2; p++){
            int nq = nq8 + 8 * p;
            float vv[4] = { rb[p].x, rb[p].y, rb[p].z, rb[p].w };
            float ww[4];
#pragma unroll
            for (int m = 0; m < 4; m++){
                int jj = (r + m) & 3;
                float s = vv[(r - m) & 3];
                ww[jj] = __shfl_sync(0xffffffffu, s, (lane & ~3) | jj);
            }
            float4 o4 = make_float4(to_tf32(ww[0]), to_tf32(ww[1]),
                                    to_tf32(ww[2]), to_tf32(ww[3]));
            *(float4*)&Bs_[(4*nq + r) * PADK + 4*kq] = o4;
        }
    };

    // prologue: LDG chunk 0 + STS stage 0
#pragma unroll
    for (int p = 0; p < 4; p++)
        ra[p] = *(const float4*)(Ag + (size_t)(32*p + arow) * K + ak4);
#pragma unroll
    for (int p = 0; p < 2; p++)
        rb[p] = *(const float4*)(Bg + (size_t)(4*kq + r) * Nn + 4*(nq8 + 8*p));
    store_stage(0);

    for (int c = 0; c < NC; c++){
        const int s = c & 1;
        __syncthreads();

        if (c + 1 < NC){
            const float* Ac = Ag + (size_t)(c + 1) * 32;
#pragma unroll
            for (int p = 0; p < 4; p++)
                ra[p] = *(const float4*)(Ac + (size_t)(32*p + arow) * K + ak4);
            const float* Bc = Bg + (size_t)(c + 1) * 32 * Nn;
#pragma unroll
            for (int p = 0; p < 2; p++)
                rb[p] = *(const float4*)(Bc + (size_t)(4*kq + r) * Nn + 4*(nq8 + 8*p));
        }

        // compute chunk c from stage s; fragment loads pipelined over ksteps
        const uint32_t sbase = smem_u + (uint32_t)s * STG_BYTES;

        uint32_t af[2][8], bf[2][2][4];
        ldm4(&af[0][0], sbase + a_rel[0]);
        ldm4(&af[0][4], sbase + a_rel[1]);
        ldm4(bf[0][0],  sbase + b_rel[0]);
        ldm4(bf[0][1],  sbase + b_rel[1]);
#pragma unroll
        for (int ks = 0; ks < 4; ks++){
            const int b = ks & 1, nb = b ^ 1;
            if (ks < 3){
                ldm4(&af[nb][0], sbase + a_rel[0] + (ks+1)*32);
                ldm4(&af[nb][4], sbase + a_rel[1] + (ks+1)*32);
                ldm4(bf[nb][0],  sbase + b_rel[0] + (ks+1)*32);
                ldm4(bf[nb][1],  sbase + b_rel[1] + (ks+1)*32);
            }
#pragma unroll
            for (int mt = 0; mt < 2; mt++)
#pragma unroll
                for (int np16 = 0; np16 < 2; np16++){
                    mma_tf32(acc[mt][2*np16 + 0], &af[b][4*mt], &bf[b][np16][0]);
                    mma_tf32(acc[mt][2*np16 + 1], &af[b][4*mt], &bf[b][np16][2]);
                }
        }

        // store chunk c+1 into the other stage
        if (c + 1 < NC) store_stage(s ^ 1);
    }

    // epilogue: direct float2 stores with bias (+ReLU)
#pragma unroll
    for (int mt = 0; mt < 2; mt++){
        int row0 = mbase + warp_m * 32 + mt * 16 + g;
#pragma unroll
        for (int np = 0; np < 4; np++){
            int col = nbase + warp_n * 32 + np * 8 + 2 * tig;
            float b0 = bias[col], b1 = bias[col + 1];
            float2 v0 = make_float2(acc[mt][np][0] + b0, acc[mt][np][1] + b1);
            float2 v1 = make_float2(acc[mt][np][2] + b0, acc[mt][np][3] + b1);
            if (RELU){
                v0.x = fmaxf(v0.x, 0.f); v0.y = fmaxf(v0.y, 0.f);
                v1.x = fmaxf(v1.x, 0.f); v1.y = fmaxf(v1.y, 0.f);
            }
            *(float2*)&C[(size_t)row0 * Nn + col]       = v0;
            *(float2*)&C[(size_t)(row0 + 8) * Nn + col] = v1;
        }
    }
}

// ---------------- causal attention (flash-style, fp32) ----------------------
#define ATTN_SMEM ((128*65 + 64*65 + 64*65 + 128*65) * 4)

__global__ void __launch_bounds__(128)
attn_kernel(const float* __restrict__ q, const float* __restrict__ k,
            const float* __restrict__ v, float* __restrict__ o)
{
    extern __shared__ float sm[];
    float* qs  = sm;
    float* ks  = qs + 128 * 65;
    float* vs  = ks + 64 * 65;
    float* scs = vs + 64 * 65;

    int n  = blockIdx.z;
    int h  = blockIdx.y;
    int qt = blockIdx.x;
    int tid = threadIdx.x;
    int r = qt * 128 + tid;

    for (int i = tid; i < 128 * 16; i += 128) {
        int row = i >> 4, c4 = (i & 15) * 4;
        float4 t = *(const float4*)(q + ((size_t)(n * SEQ + qt * 128 + row)) * DM + h * HDIM + c4);
        qs[row * 65 + c4 + 0] = t.x; qs[row * 65 + c4 + 1] = t.y;
        qs[row * 65 + c4 + 2] = t.z; qs[row * 65 + c4 + 3] = t.w;
    }
    __syncthreads();

    float qreg[64];
#pragma unroll
    for (int d = 0; d < 64; d++) qreg[d] = qs[tid * 65 + d] * 0.125f;

    float m = -1e30f, l = 0.f;
    float acc[64];
#pragma unroll
    for (int d = 0; d < 64; d++) acc[d] = 0.f;

    int smax = qt * 128 + 127;
    for (int s0 = 0; s0 <= smax; s0 += 64) {
        for (int i = tid; i < 64 * 16; i += 128) {
            int row = i >> 4, c4 = (i & 15) * 4;
            size_t base = ((size_t)(n * SEQ + s0 + row)) * DM + h * HDIM + c4;
            float4 kk = *(const float4*)(k + base);
            ks[row * 65 + c4 + 0] = kk.x; ks[row * 65 + c4 + 1] = kk.y;
            ks[row * 65 + c4 + 2] = kk.z; ks[row * 65 + c4 + 3] = kk.w;
            float4 vv = *(const float4*)(v + base);
            vs[row * 65 + c4 + 0] = vv.x; vs[row * 65 + c4 + 1] = vv.y;
            vs[row * 65 + c4 + 2] = vv.z; vs[row * 65 + c4 + 3] = vv.w;
        }
        __syncthreads();

        float tmax = -1e30f;
        for (int s = 0; s < 64; s++) {
            float sc;
            if (s0 + s > r) {
                sc = -1e30f;
            } else {
                sc = 0.f;
#pragma unroll
                for (int d = 0; d < 64; d++) sc += qreg[d] * ks[s * 65 + d];
            }
            scs[tid * 65 + s] = sc;
            tmax = fmaxf(tmax, sc);
        }

        float nm = fmaxf(m, tmax);
        float cf = __expf(m - nm);
        l *= cf;
#pragma unroll
        for (int d = 0; d < 64; d++) acc[d] *= cf;

        for (int s = 0; s < 64; s++) {
            float p = __expf(scs[tid * 65 + s] - nm);
            l += p;
#pragma unroll
            for (int d = 0; d < 64; d++) acc[d] += p * vs[s * 65 + d];
        }
        m = nm;
        __syncthreads();
    }

    float inv = 1.f / l;
    float* op = o + ((size_t)(n * SEQ + r)) * DM + h * HDIM;
#pragma unroll
    for (int d0 = 0; d0 < 64; d0 += 4) {
        float4 t;
        t.x = acc[d0 + 0] * inv; t.y = acc[d0 + 1] * inv;
        t.z = acc[d0 + 2] * inv; t.w = acc[d0 + 3] * inv;
        *(float4*)(op + d0) = t;
    }
}

// ---------------- residual + LayerNorm: x += LN(o)*g + b --------------------
__global__ void __launch_bounds__(256)
ln_residual(float* __restrict__ x, const float* __restrict__ o,
            const float* __restrict__ g, const float* __restrict__ b)
{
    __shared__ float red[256];
    __shared__ float s_mean, s_rstd;
    int row = blockIdx.x;
    int tid = threadIdx.x;
    const float* orow = o + (size_t)row * DM;
    float*       xrow = x + (size_t)row * DM;

    float s = 0.f;
    for (int d = tid; d < DM; d += 256) s += orow[d];
    red[tid] = s; __syncthreads();
    for (int off = 128; off > 0; off >>= 1) {
        if (tid < off) red[tid] += red[tid + off];
        __syncthreads();
    }
    if (tid == 0) s_mean = red[0] * (1.f / DM);
    __syncthreads();
    float mean = s_mean;

    float vv = 0.f;
    for (int d = tid; d < DM; d += 256) { float t = orow[d] - mean; vv += t * t; }
    red[tid] = vv; __syncthreads();
    for (int off = 128; off > 0; off >>= 1) {
        if (tid < off) red[tid] += red[tid + off];
        __syncthreads();
    }
    if (tid == 0) s_rstd = rsqrtf(red[0] * (1.f / DM) + 1e-5f);
    __syncthreads();
    float rstd = s_rstd;

    for (int d = tid; d < DM; d += 256)
        xrow[d] += (orow[d] - mean) * rstd * g[d] + b[d];
}

// ---------------- launch ----------------------------------------------------
extern "C" void kernel_launch(void* const* d_in, const int* in_sizes, int n_in,
                              void* d_out, int out_size)
{
    const int*   tokens = (const int*)  d_in[0];
    const float* emb    = (const float*)d_in[1];
    const float* pe     = (const float*)d_in[2];
    const float* Wq     = (const float*)d_in[3];
    const float* bq     = (const float*)d_in[4];
    const float* Wk     = (const float*)d_in[5];
    const float* bk     = (const float*)d_in[6];
    const float* Wv     = (const float*)d_in[7];
    const float* bv     = (const float*)d_in[8];
    const float* Wo     = (const float*)d_in[9];
    const float* bo     = (const float*)d_in[10];
    const float* g1     = (const float*)d_in[11];
    const float* be1    = (const float*)d_in[12];
    const float* W1     = (const float*)d_in[13];
    const float* b1     = (const float*)d_in[14];
    const float* W2     = (const float*)d_in[15];
    const float* b2     = (const float*)d_in[16];
    const float* g2     = (const float*)d_in[17];
    const float* be2    = (const float*)d_in[18];
    const float* Wfc    = (const float*)d_in[19];
    const float* bfc    = (const float*)d_in[20];
    float* out = (float*)d_out;

    float *x, *t0, *t1, *t2, *t3, *f1;
    cudaGetSymbolAddress((void**)&x,  g_x);
    cudaGetSymbolAddress((void**)&t0, g_t0);
    cudaGetSymbolAddress((void**)&t1, g_t1);
    cudaGetSymbolAddress((void**)&t2, g_t2);
    cudaGetSymbolAddress((void**)&t3, g_t3);
    cudaGetSymbolAddress((void**)&f1, g_f1);

    cudaFuncSetAttribute(attn_kernel,
                         cudaFuncAttributeMaxDynamicSharedMemorySize, ATTN_SMEM);
    cudaFuncSetAttribute(tf32_gemm<false>,
                         cudaFuncAttributeMaxDynamicSharedMemorySize, GEMM_SMEM);
    cudaFuncSetAttribute(tf32_gemm<true>,
                         cudaFuncAttributeMaxDynamicSharedMemorySize, GEMM_SMEM);

    embed_kernel<<<(MROWS * DM + 255) / 256, 256>>>(tokens, emb, pe, x);

    dim3 gDD(MROWS / 128, DM / 64);     // (16, 16)
    dim3 gDF(MROWS / 128, DFF / 64);    // (16, 64)
    dim3 gAttn(SEQ / 128, NH, BATCH);

    for (int l = 0; l < NL; l++) {
        const float* wq = Wq + (size_t)l * DM * DM;
        const float* wk = Wk + (size_t)l * DM * DM;
        const float* wv = Wv + (size_t)l * DM * DM;
        const float* wo = Wo + (size_t)l * DM * DM;
        const float* w1 = W1 + (size_t)l * DM * DFF;
        const float* w2 = W2 + (size_t)l * DFF * DM;

        tf32_gemm<false><<<gDD, 256, GEMM_SMEM>>>(x, wq, bq + l * DM, t0, DM, DM);
        tf32_gemm<false><<<gDD, 256, GEMM_SMEM>>>(x, wk, bk + l * DM, t1, DM, DM);
        tf32_gemm<false><<<gDD, 256, GEMM_SMEM>>>(x, wv, bv + l * DM, t2, DM, DM);

        attn_kernel<<<gAttn, 128, ATTN_SMEM>>>(t0, t1, t2, t3);

        tf32_gemm<false><<<gDD, 256, GEMM_SMEM>>>(t3, wo, bo + l * DM, t0, DM, DM);
        ln_residual<<<MROWS, 256>>>(x, t0, g1 + l * DM, be1 + l * DM);

        tf32_gemm<true ><<<gDF, 256, GEMM_SMEM>>>(x,  w1, b1 + l * DFF, f1, DFF, DM);
        tf32_gemm<false><<<gDD, 256, GEMM_SMEM>>>(f1, w2, b2 + l * DM,  t0, DM, DFF);
        ln_residual<<<MROWS, 256>>>(x, t0, g2 + l * DM, be2 + l * DM);
    }

    dim3 gV(MROWS / 128, VOCAB / 64);   // (16, 500)
    tf32_gemm<false><<<gV, 256, GEMM_SMEM>>>(x, Wfc, bfc, out, VOCAB, DM);
}

// round 8
// speedup vs baseline: 1.4347x; 1.4347x over previous
#include <cuda_runtime.h>
#include <cuda_bf16.h>
#include <math.h>
#include <stdint.h>

#define BATCH 4
#define SEQ   512
#define DM    1024
#define NH    16
#define NL    8
#define VOCAB 32000
#define HDIM  64
#define DFF   4096
#define MROWS (BATCH*SEQ)

__device__ float g_x [MROWS*DM];
__device__ float g_t0[MROWS*DM];
__device__ float g_t1[MROWS*DM];
__device__ float g_t2[MROWS*DM];
__device__ float g_t3[MROWS*DM];
__device__ float g_f1[MROWS*DFF];

__global__ void embed_kernel(const int* __restrict__ tokens,
                             const float* __restrict__ emb,
                             const float* __restrict__ pe,
                             float* __restrict__ x)
{
    int idx = blockIdx.x * blockDim.x + threadIdx.x;
    if (idx >= MROWS * DM) return;
    int d  = idx % DM;
    int nt = idx / DM;
    int n  = nt / SEQ;
    int tok = tokens[nt];
    x[idx] = emb[(size_t)tok * DM + d] + pe[(size_t)n * DM + d];
}

// ============ tf32 mma.sync GEMM (pipelined, 128x128 tile, warp 64x32) =======
// C(MxN)=A(MxK)@B(KxN)+bias (opt ReLU). BK=32, 2-stage smem ring, 256 threads.
// 8 warps in 2(M) x 4(N); warp tile 64x32. A row-major smem [128][36] (ldmatrix),
// B k-major smem [32][136] (scalar LDS fragments; pad 136 -> conflict-free).
#define PADA 36
#define PADB 136
#define A_FL (128*PADA)          // 4608 floats
#define B_FL (32*PADB)           // 4352 floats
#define STG_FL (A_FL + B_FL)     // 8960 floats
#define STG_BYTES (STG_FL*4)     // 35840
#define GEMM_SMEM (2*STG_BYTES)  // 71680

__device__ __forceinline__ uint32_t cvta_smem(const void* p){
    uint32_t a;
    asm("{ .reg .u64 t; cvta.to.shared.u64 t, %1; cvt.u32.u64 %0, t; }" : "=r"(a) : "l"(p));
    return a;
}
__device__ __forceinline__ float to_tf32(float x){
    uint32_t u;
    asm("cvt.rna.tf32.f32 %0, %1;" : "=r"(u) : "f"(x));
    return __uint_as_float(u);
}
__device__ __forceinline__ void ldm4(uint32_t* r, uint32_t addr){
    asm volatile("ldmatrix.sync.aligned.m8n8.x4.shared.b16 {%0,%1,%2,%3}, [%4];"
                 : "=r"(r[0]), "=r"(r[1]), "=r"(r[2]), "=r"(r[3]) : "r"(addr));
}
__device__ __forceinline__ void mma_tf32(float* c, const uint32_t* a, const uint32_t* b){
    asm volatile(
        "mma.sync.aligned.m16n8k8.row.col.f32.tf32.tf32.f32 "
        "{%0,%1,%2,%3}, {%4,%5,%6,%7}, {%8,%9}, {%0,%1,%2,%3};"
        : "+f"(c[0]), "+f"(c[1]), "+f"(c[2]), "+f"(c[3])
        : "r"(a[0]), "r"(a[1]), "r"(a[2]), "r"(a[3]), "r"(b[0]), "r"(b[1]));
}

template<bool RELU>
__global__ void __launch_bounds__(256, 1)
tf32_gemm(const float* __restrict__ A, const float* __restrict__ B,
          const float* __restrict__ bias, float* __restrict__ C,
          int Nn, int K)
{
    extern __shared__ float smem[];
    const int tid = threadIdx.x, lane = tid & 31, warp = tid >> 5;
    const int warp_m = warp & 1, warp_n = warp >> 1;
    const int mbase = blockIdx.x * 128, nbase = blockIdx.y * 128;

    const float* Ag = A + (size_t)mbase * K;
    const float* Bg = B + nbase;
    const int NC = K >> 5;

    // global load mappings
    const int arow = tid >> 3, ak4 = (tid & 7) << 2;   // A: rows 32 apart x4, 4 floats
    const int brow = tid >> 3, bc4 = tid & 7;          // B: 1 row, float4 cols bc4+8p

    // fragment mappings
    const int g = lane >> 2, tig = lane & 3;
    const int sel = lane >> 3, l7 = lane & 7;
    const uint32_t smem_u = cvta_smem(smem);
    uint32_t a_rel[4];
#pragma unroll
    for (int mt = 0; mt < 4; mt++){
        int row = warp_m * 64 + mt * 16 + (sel & 1) * 8 + l7;
        int col = (sel >> 1) * 4;
        a_rel[mt] = (uint32_t)(row * PADA + col) * 4u;
    }
    const int bidx = tig * PADB + warp_n * 32 + g;     // float idx into B stage

    float acc[4][4][4];
#pragma unroll
    for (int mt = 0; mt < 4; mt++)
#pragma unroll
        for (int np = 0; np < 4; np++)
#pragma unroll
            for (int i = 0; i < 4; i++) acc[mt][np][i] = 0.f;

    float4 ra[4], rb[4];

    auto store_stage = [&](int stage){
        float* As_ = smem + stage * STG_FL;
        float* Bs_ = As_ + A_FL;
#pragma unroll
        for (int p = 0; p < 4; p++){
            float4 v = ra[p];
            v.x = to_tf32(v.x); v.y = to_tf32(v.y); v.z = to_tf32(v.z); v.w = to_tf32(v.w);
            *(float4*)&As_[(32*p + arow) * PADA + ak4] = v;
        }
#pragma unroll
        for (int p = 0; p < 4; p++){
            float4 v = rb[p];
            v.x = to_tf32(v.x); v.y = to_tf32(v.y); v.z = to_tf32(v.z); v.w = to_tf32(v.w);
            *(float4*)&Bs_[brow * PADB + (bc4 + 8*p) * 4] = v;
        }
    };

    // prologue: LDG chunk 0 + STS stage 0
#pragma unroll
    for (int p = 0; p < 4; p++)
        ra[p] = *(const float4*)(Ag + (size_t)(32*p + arow) * K + ak4);
#pragma unroll
    for (int p = 0; p < 4; p++)
        rb[p] = *(const float4*)(Bg + (size_t)brow * Nn + (bc4 + 8*p) * 4);
    store_stage(0);

    for (int c = 0; c < NC; c++){
        const int s = c & 1;
        __syncthreads();

        if (c + 1 < NC){
            const float* Ac = Ag + (size_t)(c + 1) * 32;
#pragma unroll
            for (int p = 0; p < 4; p++)
                ra[p] = *(const float4*)(Ac + (size_t)(32*p + arow) * K + ak4);
            const float* Bc = Bg + (size_t)(c + 1) * 32 * Nn;
#pragma unroll
            for (int p = 0; p < 4; p++)
                rb[p] = *(const float4*)(Bc + (size_t)brow * Nn + (bc4 + 8*p) * 4);
        }

        // compute chunk c from stage s; fragment loads pipelined over ksteps
        const uint32_t sbase = smem_u + (uint32_t)s * STG_BYTES;
        const float* Bst = smem + s * STG_FL + A_FL;

        uint32_t af[2][16], bf[2][8];
#pragma unroll
        for (int mt = 0; mt < 4; mt++) ldm4(&af[0][4*mt], sbase + a_rel[mt]);
#pragma unroll
        for (int np = 0; np < 4; np++){
            bf[0][2*np]     = __float_as_uint(Bst[bidx + np*8]);
            bf[0][2*np + 1] = __float_as_uint(Bst[bidx + np*8 + 4*PADB]);
        }
#pragma unroll
        for (int ks = 0; ks < 4; ks++){
            const int b = ks & 1, nb = b ^ 1;
            if (ks < 3){
#pragma unroll
                for (int mt = 0; mt < 4; mt++)
                    ldm4(&af[nb][4*mt], sbase + a_rel[mt] + (ks+1)*32);
                const float* Bk = Bst + (ks+1)*8*PADB;
#pragma unroll
                for (int np = 0; np < 4; np++){
                    bf[nb][2*np]     = __float_as_uint(Bk[bidx + np*8]);
                    bf[nb][2*np + 1] = __float_as_uint(Bk[bidx + np*8 + 4*PADB]);
                }
            }
#pragma unroll
            for (int mt = 0; mt < 4; mt++)
#pragma unroll
                for (int np = 0; np < 4; np++)
                    mma_tf32(acc[mt][np], &af[b][4*mt], &bf[b][2*np]);
        }

        if (c + 1 < NC) store_stage(s ^ 1);
    }

    // epilogue: direct float2 stores with bias (+ReLU)
#pragma unroll
    for (int mt = 0; mt < 4; mt++){
        int row0 = mbase + warp_m * 64 + mt * 16 + g;
#pragma unroll
        for (int np = 0; np < 4; np++){
            int col = nbase + warp_n * 32 + np * 8 + 2 * tig;
            float b0 = bias[col], b1 = bias[col + 1];
            float2 v0 = make_float2(acc[mt][np][0] + b0, acc[mt][np][1] + b1);
            float2 v1 = make_float2(acc[mt][np][2] + b0, acc[mt][np][3] + b1);
            if (RELU){
                v0.x = fmaxf(v0.x, 0.f); v0.y = fmaxf(v0.y, 0.f);
                v1.x = fmaxf(v1.x, 0.f); v1.y = fmaxf(v1.y, 0.f);
            }
            *(float2*)&C[(size_t)row0 * Nn + col]       = v0;
            *(float2*)&C[(size_t)(row0 + 8) * Nn + col] = v1;
        }
    }
}

// ---------------- causal attention (flash-style, fp32) ----------------------
#define ATTN_SMEM ((128*65 + 64*65 + 64*65 + 128*65) * 4)

__global__ void __launch_bounds__(128)
attn_kernel(const float* __restrict__ q, const float* __restrict__ k,
            const float* __restrict__ v, float* __restrict__ o)
{
    extern __shared__ float sm[];
    float* qs  = sm;
    float* ks  = qs + 128 * 65;
    float* vs  = ks + 64 * 65;
    float* scs = vs + 64 * 65;

    int n  = blockIdx.z;
    int h  = blockIdx.y;
    int qt = blockIdx.x;
    int tid = threadIdx.x;
    int r = qt * 128 + tid;

    for (int i = tid; i < 128 * 16; i += 128) {
        int row = i >> 4, c4 = (i & 15) * 4;
        float4 t = *(const float4*)(q + ((size_t)(n * SEQ + qt * 128 + row)) * DM + h * HDIM + c4);
        qs[row * 65 + c4 + 0] = t.x; qs[row * 65 + c4 + 1] = t.y;
        qs[row * 65 + c4 + 2] = t.z; qs[row * 65 + c4 + 3] = t.w;
    }
    __syncthreads();

    float qreg[64];
#pragma unroll
    for (int d = 0; d < 64; d++) qreg[d] = qs[tid * 65 + d] * 0.125f;

    float m = -1e30f, l = 0.f;
    float acc[64];
#pragma unroll
    for (int d = 0; d < 64; d++) acc[d] = 0.f;

    int smax = qt * 128 + 127;
    for (int s0 = 0; s0 <= smax; s0 += 64) {
        for (int i = tid; i < 64 * 16; i += 128) {
            int row = i >> 4, c4 = (i & 15) * 4;
            size_t base = ((size_t)(n * SEQ + s0 + row)) * DM + h * HDIM + c4;
            float4 kk = *(const float4*)(k + base);
            ks[row * 65 + c4 + 0] = kk.x; ks[row * 65 + c4 + 1] = kk.y;
            ks[row * 65 + c4 + 2] = kk.z; ks[row * 65 + c4 + 3] = kk.w;
            float4 vv = *(const float4*)(v + base);
            vs[row * 65 + c4 + 0] = vv.x; vs[row * 65 + c4 + 1] = vv.y;
            vs[row * 65 + c4 + 2] = vv.z; vs[row * 65 + c4 + 3] = vv.w;
        }
        __syncthreads();

        float tmax = -1e30f;
        for (int s = 0; s < 64; s++) {
            float sc;
            if (s0 + s > r) {
                sc = -1e30f;
            } else {
                sc = 0.f;
#pragma unroll
                for (int d = 0; d < 64; d++) sc += qreg[d] * ks[s * 65 + d];
            }
            scs[tid * 65 + s] = sc;
            tmax = fmaxf(tmax, sc);
        }

        float nm = fmaxf(m, tmax);
        float cf = __expf(m - nm);
        l *= cf;
#pragma unroll
        for (int d = 0; d < 64; d++) acc[d] *= cf;

        for (int s = 0; s < 64; s++) {
            float p = __expf(scs[tid * 65 + s] - nm);
            l += p;
#pragma unroll
            for (int d = 0; d < 64; d++) acc[d] += p * vs[s * 65 + d];
        }
        m = nm;
        __syncthreads();
    }

    float inv = 1.f / l;
    float* op = o + ((size_t)(n * SEQ + r)) * DM + h * HDIM;
#pragma unroll
    for (int d0 = 0; d0 < 64; d0 += 4) {
        float4 t;
        t.x = acc[d0 + 0] * inv; t.y = acc[d0 + 1] * inv;
        t.z = acc[d0 + 2] * inv; t.w = acc[d0 + 3] * inv;
        *(float4*)(op + d0) = t;
    }
}

// ---------------- residual + LayerNorm: x += LN(o)*g + b --------------------
__global__ void __launch_bounds__(256)
ln_residual(float* __restrict__ x, const float* __restrict__ o,
            const float* __restrict__ g, const float* __restrict__ b)
{
    __shared__ float red[256];
    __shared__ float s_mean, s_rstd;
    int row = blockIdx.x;
    int tid = threadIdx.x;
    const float* orow = o + (size_t)row * DM;
    float*       xrow = x + (size_t)row * DM;

    float s = 0.f;
    for (int d = tid; d < DM; d += 256) s += orow[d];
    red[tid] = s; __syncthreads();
    for (int off = 128; off > 0; off >>= 1) {
        if (tid < off) red[tid] += red[tid + off];
        __syncthreads();
    }
    if (tid == 0) s_mean = red[0] * (1.f / DM);
    __syncthreads();
    float mean = s_mean;

    float vv = 0.f;
    for (int d = tid; d < DM; d += 256) { float t = orow[d] - mean; vv += t * t; }
    red[tid] = vv; __syncthreads();
    for (int off = 128; off > 0; off >>= 1) {
        if (tid < off) red[tid] += red[tid + off];
        __syncthreads();
    }
    if (tid == 0) s_rstd = rsqrtf(red[0] * (1.f / DM) + 1e-5f);
    __syncthreads();
    float rstd = s_rstd;

    for (int d = tid; d < DM; d += 256)
        xrow[d] += (orow[d] - mean) * rstd * g[d] + b[d];
}

// ---------------- launch ----------------------------------------------------
extern "C" void kernel_launch(void* const* d_in, const int* in_sizes, int n_in,
                              void* d_out, int out_size)
{
    const int*   tokens = (const int*)  d_in[0];
    const float* emb    = (const float*)d_in[1];
    const float* pe     = (const float*)d_in[2];
    const float* Wq     = (const float*)d_in[3];
    const float* bq     = (const float*)d_in[4];
    const float* Wk     = (const float*)d_in[5];
    const float* bk     = (const float*)d_in[6];
    const float* Wv     = (const float*)d_in[7];
    const float* bv     = (const float*)d_in[8];
    const float* Wo     = (const float*)d_in[9];
    const float* bo     = (const float*)d_in[10];
    const float* g1     = (const float*)d_in[11];
    const float* be1    = (const float*)d_in[12];
    const float* W1     = (const float*)d_in[13];
    const float* b1     = (const float*)d_in[14];
    const float* W2     = (const float*)d_in[15];
    const float* b2     = (const float*)d_in[16];
    const float* g2     = (const float*)d_in[17];
    const float* be2    = (const float*)d_in[18];
    const float* Wfc    = (const float*)d_in[19];
    const float* bfc    = (const float*)d_in[20];
    float* out = (float*)d_out;

    float *x, *t0, *t1, *t2, *t3, *f1;
    cudaGetSymbolAddress((void**)&x,  g_x);
    cudaGetSymbolAddress((void**)&t0, g_t0);
    cudaGetSymbolAddress((void**)&t1, g_t1);
    cudaGetSymbolAddress((void**)&t2, g_t2);
    cudaGetSymbolAddress((void**)&t3, g_t3);
    cudaGetSymbolAddress((void**)&f1, g_f1);

    cudaFuncSetAttribute(attn_kernel,
                         cudaFuncAttributeMaxDynamicSharedMemorySize, ATTN_SMEM);
    cudaFuncSetAttribute(tf32_gemm<false>,
                         cudaFuncAttributeMaxDynamicSharedMemorySize, GEMM_SMEM);
    cudaFuncSetAttribute(tf32_gemm<true>,
                         cudaFuncAttributeMaxDynamicSharedMemorySize, GEMM_SMEM);

    embed_kernel<<<(MROWS * DM + 255) / 256, 256>>>(tokens, emb, pe, x);

    dim3 gDD(MROWS / 128, DM / 128);    // (16, 8)
    dim3 gDF(MROWS / 128, DFF / 128);   // (16, 32)
    dim3 gAttn(SEQ / 128, NH, BATCH);

    for (int l = 0; l < NL; l++) {
        const float* wq = Wq + (size_t)l * DM * DM;
        const float* wk = Wk + (size_t)l * DM * DM;
        const float* wv = Wv + (size_t)l * DM * DM;
        const float* wo = Wo + (size_t)l * DM * DM;
        const float* w1 = W1 + (size_t)l * DM * DFF;
        const float* w2 = W2 + (size_t)l * DFF * DM;

        tf32_gemm<false><<<gDD, 256, GEMM_SMEM>>>(x, wq, bq + l * DM, t0, DM, DM);
        tf32_gemm<false><<<gDD, 256, GEMM_SMEM>>>(x, wk, bk + l * DM, t1, DM, DM);
        tf32_gemm<false><<<gDD, 256, GEMM_SMEM>>>(x, wv, bv + l * DM, t2, DM, DM);

        attn_kernel<<<gAttn, 128, ATTN_SMEM>>>(t0, t1, t2, t3);

        tf32_gemm<false><<<gDD, 256, GEMM_SMEM>>>(t3, wo, bo + l * DM, t0, DM, DM);
        ln_residual<<<MROWS, 256>>>(x, t0, g1 + l * DM, be1 + l * DM);

        tf32_gemm<true ><<<gDF, 256, GEMM_SMEM>>>(x,  w1, b1 + l * DFF, f1, DFF, DM);
        tf32_gemm<false><<<gDD, 256, GEMM_SMEM>>>(f1, w2, b2 + l * DM,  t0, DM, DFF);
        ln_residual<<<MROWS, 256>>>(x, t0, g2 + l * DM, be2 + l * DM);
    }

    dim3 gV(MROWS / 128, VOCAB / 128);  // (16, 250)
    tf32_gemm<false><<<gV, 256, GEMM_SMEM>>>(x, Wfc, bfc, out, VOCAB, DM);
}

// round 9
// speedup vs baseline: 1.6840x; 1.1738x over previous
#include <cuda_runtime.h>
#include <cuda_bf16.h>
#include <cuda_fp16.h>
#include <math.h>
#include <stdint.h>

#define BATCH 4
#define SEQ   512
#define DM    1024
#define NH    16
#define NL    8
#define VOCAB 32000
#define HDIM  64
#define DFF   4096
#define MROWS (BATCH*SEQ)

__device__ float g_x [MROWS*DM];
__device__ float g_t0[MROWS*DM];
__device__ float g_t1[MROWS*DM];
__device__ float g_t2[MROWS*DM];
__device__ float g_t3[MROWS*DM];
__device__ float g_f1[MROWS*DFF];

__global__ void embed_kernel(const int* __restrict__ tokens,
                             const float* __restrict__ emb,
                             const float* __restrict__ pe,
                             float* __restrict__ x)
{
    int idx = blockIdx.x * blockDim.x + threadIdx.x;
    if (idx >= MROWS * DM) return;
    int d  = idx % DM;
    int nt = idx / DM;
    int n  = nt / SEQ;
    int tok = tokens[nt];
    x[idx] = emb[(size_t)tok * DM + d] + pe[(size_t)n * DM + d];
}

// ============ fp16 mma.sync GEMM (pipelined, 128x128 tile, warp 64x32) =======
// C(MxN)=A(MxK)@B(KxN)+bias (opt ReLU). BK=32, 2-stage smem ring, 256 threads.
// 8 warps 2(M)x4(N); warp tile 64x32. fp16 operands (rn-converted), fp32 accum.
// A row-major smem [128][40] halves (ldmatrix x4); B k-major smem [32][136]
// halves (ldmatrix x4 TRANS -> col-major B fragments, no transpose needed).
#define PADA 40      // halves per A row (80B; conflict-free ldmatrix)
#define PADB 136     // halves per B row (272B; conflict-free trans ldmatrix)
#define A_HL (128*PADA)              // 5120 halves
#define B_HL (32*PADB)               // 4352 halves
#define STG_HL (A_HL + B_HL)         // 9472 halves
#define STG_BYTES (STG_HL*2)         // 18944
#define GEMM_SMEM (2*STG_BYTES)      // 37888

__device__ __forceinline__ uint32_t cvta_smem(const void* p){
    uint32_t a;
    asm("{ .reg .u64 t; cvta.to.shared.u64 t, %1; cvt.u32.u64 %0, t; }" : "=r"(a) : "l"(p));
    return a;
}
__device__ __forceinline__ void ldm4(uint32_t* r, uint32_t addr){
    asm volatile("ldmatrix.sync.aligned.m8n8.x4.shared.b16 {%0,%1,%2,%3}, [%4];"
                 : "=r"(r[0]), "=r"(r[1]), "=r"(r[2]), "=r"(r[3]) : "r"(addr));
}
__device__ __forceinline__ void ldm4t(uint32_t* r, uint32_t addr){
    asm volatile("ldmatrix.sync.aligned.m8n8.x4.trans.shared.b16 {%0,%1,%2,%3}, [%4];"
                 : "=r"(r[0]), "=r"(r[1]), "=r"(r[2]), "=r"(r[3]) : "r"(addr));
}
__device__ __forceinline__ void mma_f16(float* c, const uint32_t* a, const uint32_t* b){
    asm volatile(
        "mma.sync.aligned.m16n8k16.row.col.f32.f16.f16.f32 "
        "{%0,%1,%2,%3}, {%4,%5,%6,%7}, {%8,%9}, {%0,%1,%2,%3};"
        : "+f"(c[0]), "+f"(c[1]), "+f"(c[2]), "+f"(c[3])
        : "r"(a[0]), "r"(a[1]), "r"(a[2]), "r"(a[3]), "r"(b[0]), "r"(b[1]));
}
__device__ __forceinline__ uint32_t h2(float x, float y){
    __half2 h = __floats2half2_rn(x, y);
    return *(uint32_t*)&h;
}

template<bool RELU>
__global__ void __launch_bounds__(256, 1)
hgemm(const float* __restrict__ A, const float* __restrict__ B,
      const float* __restrict__ bias, float* __restrict__ C,
      int Nn, int K)
{
    extern __shared__ __half smem[];
    const int tid = threadIdx.x, lane = tid & 31, warp = tid >> 5;
    const int warp_m = warp & 1, warp_n = warp >> 1;
    const int mbase = blockIdx.x * 128, nbase = blockIdx.y * 128;

    const float* Ag = A + (size_t)mbase * K;
    const float* Bg = B + nbase;
    const int NC = K >> 5;

    // global load mappings
    const int arow = tid >> 3, ak4 = (tid & 7) << 2;   // A: rows 32 apart x4, 4 floats
    const int brow = tid >> 3, bc4 = tid & 7;          // B: 1 row, float4 cols bc4+8p

    // fragment mappings
    const int g = lane >> 2, tig = lane & 3;
    const int sel = lane >> 3, l7 = lane & 7;
    const uint32_t smem_u = cvta_smem(smem);
    uint32_t a_rel[4], b_rel[2];
#pragma unroll
    for (int mt = 0; mt < 4; mt++){
        int row = warp_m * 64 + mt * 16 + (sel & 1) * 8 + l7;
        a_rel[mt] = (uint32_t)(row * (PADA*2)) + (uint32_t)((sel >> 1) * 16);
    }
#pragma unroll
    for (int np2 = 0; np2 < 2; np2++){
        int krow = (sel & 1) * 8 + l7;
        int ncol = warp_n * 32 + np2 * 16 + (sel >> 1) * 8;
        b_rel[np2] = (uint32_t)(A_HL*2) + (uint32_t)(krow * (PADB*2)) + (uint32_t)(ncol * 2);
    }

    float acc[4][4][4];
#pragma unroll
    for (int mt = 0; mt < 4; mt++)
#pragma unroll
        for (int np = 0; np < 4; np++)
#pragma unroll
            for (int i = 0; i < 4; i++) acc[mt][np][i] = 0.f;

    float4 ra[4], rb[4];

    auto store_stage = [&](int stage){
        __half* st = smem + stage * STG_HL;
#pragma unroll
        for (int p = 0; p < 4; p++){
            uint2 v = make_uint2(h2(ra[p].x, ra[p].y), h2(ra[p].z, ra[p].w));
            *(uint2*)&st[(32*p + arow) * PADA + ak4] = v;
        }
        __half* bs = st + A_HL;
#pragma unroll
        for (int p = 0; p < 4; p++){
            uint2 v = make_uint2(h2(rb[p].x, rb[p].y), h2(rb[p].z, rb[p].w));
            *(uint2*)&bs[brow * PADB + (bc4 + 8*p) * 4] = v;
        }
    };

    // prologue: LDG chunk 0 + STS stage 0
#pragma unroll
    for (int p = 0; p < 4; p++)
        ra[p] = *(const float4*)(Ag + (size_t)(32*p + arow) * K + ak4);
#pragma unroll
    for (int p = 0; p < 4; p++)
        rb[p] = *(const float4*)(Bg + (size_t)brow * Nn + (bc4 + 8*p) * 4);
    store_stage(0);

    for (int c = 0; c < NC; c++){
        const int s = c & 1;
        __syncthreads();

        if (c + 1 < NC){
            const float* Ac = Ag + (size_t)(c + 1) * 32;
#pragma unroll
            for (int p = 0; p < 4; p++)
                ra[p] = *(const float4*)(Ac + (size_t)(32*p + arow) * K + ak4);
            const float* Bc = Bg + (size_t)(c + 1) * 32 * Nn;
#pragma unroll
            for (int p = 0; p < 4; p++)
                rb[p] = *(const float4*)(Bc + (size_t)brow * Nn + (bc4 + 8*p) * 4);
        }

        // compute chunk c from stage s: 2 ksteps of k16, frag loads pipelined
        const uint32_t sbase = smem_u + (uint32_t)s * STG_BYTES;

        uint32_t af[2][16], bf[2][8];
#pragma unroll
        for (int mt = 0; mt < 4; mt++) ldm4(&af[0][4*mt], sbase + a_rel[mt]);
#pragma unroll
        for (int np2 = 0; np2 < 2; np2++) ldm4t(&bf[0][4*np2], sbase + b_rel[np2]);

#pragma unroll
        for (int ks = 0; ks < 2; ks++){
            const int b = ks & 1, nb = b ^ 1;
            if (ks < 1){
#pragma unroll
                for (int mt = 0; mt < 4; mt++)
                    ldm4(&af[nb][4*mt], sbase + a_rel[mt] + 32);       // +16 halves (k16)
#pragma unroll
                for (int np2 = 0; np2 < 2; np2++)
                    ldm4t(&bf[nb][4*np2], sbase + b_rel[np2] + 16*PADB*2); // +16 k rows
            }
#pragma unroll
            for (int mt = 0; mt < 4; mt++)
#pragma unroll
                for (int np = 0; np < 4; np++)
                    mma_f16(acc[mt][np], &af[b][4*mt], &bf[b][2*np]);
        }

        if (c + 1 < NC) store_stage(s ^ 1);
    }

    // epilogue: direct float2 stores with bias (+ReLU)
#pragma unroll
    for (int mt = 0; mt < 4; mt++){
        int row0 = mbase + warp_m * 64 + mt * 16 + g;
#pragma unroll
        for (int np = 0; np < 4; np++){
            int col = nbase + warp_n * 32 + np * 8 + 2 * tig;
            float b0 = bias[col], b1 = bias[col + 1];
            float2 v0 = make_float2(acc[mt][np][0] + b0, acc[mt][np][1] + b1);
            float2 v1 = make_float2(acc[mt][np][2] + b0, acc[mt][np][3] + b1);
            if (RELU){
                v0.x = fmaxf(v0.x, 0.f); v0.y = fmaxf(v0.y, 0.f);
                v1.x = fmaxf(v1.x, 0.f); v1.y = fmaxf(v1.y, 0.f);
            }
            *(float2*)&C[(size_t)row0 * Nn + col]       = v0;
            *(float2*)&C[(size_t)(row0 + 8) * Nn + col] = v1;
        }
    }
}

// ---------------- causal attention (flash-style, fp32) ----------------------
#define ATTN_SMEM ((128*65 + 64*65 + 64*65 + 128*65) * 4)

__global__ void __launch_bounds__(128)
attn_kernel(const float* __restrict__ q, const float* __restrict__ k,
            const float* __restrict__ v, float* __restrict__ o)
{
    extern __shared__ float sm[];
    float* qs  = sm;
    float* ks  = qs + 128 * 65;
    float* vs  = ks + 64 * 65;
    float* scs = vs + 64 * 65;

    int n  = blockIdx.z;
    int h  = blockIdx.y;
    int qt = blockIdx.x;
    int tid = threadIdx.x;
    int r = qt * 128 + tid;

    for (int i = tid; i < 128 * 16; i += 128) {
        int row = i >> 4, c4 = (i & 15) * 4;
        float4 t = *(const float4*)(q + ((size_t)(n * SEQ + qt * 128 + row)) * DM + h * HDIM + c4);
        qs[row * 65 + c4 + 0] = t.x; qs[row * 65 + c4 + 1] = t.y;
        qs[row * 65 + c4 + 2] = t.z; qs[row * 65 + c4 + 3] = t.w;
    }
    __syncthreads();

    float qreg[64];
#pragma unroll
    for (int d = 0; d < 64; d++) qreg[d] = qs[tid * 65 + d] * 0.125f;

    float m = -1e30f, l = 0.f;
    float acc[64];
#pragma unroll
    for (int d = 0; d < 64; d++) acc[d] = 0.f;

    int smax = qt * 128 + 127;
    for (int s0 = 0; s0 <= smax; s0 += 64) {
        for (int i = tid; i < 64 * 16; i += 128) {
            int row = i >> 4, c4 = (i & 15) * 4;
            size_t base = ((size_t)(n * SEQ + s0 + row)) * DM + h * HDIM + c4;
            float4 kk = *(const float4*)(k + base);
            ks[row * 65 + c4 + 0] = kk.x; ks[row * 65 + c4 + 1] = kk.y;
            ks[row * 65 + c4 + 2] = kk.z; ks[row * 65 + c4 + 3] = kk.w;
            float4 vv = *(const float4*)(v + base);
            vs[row * 65 + c4 + 0] = vv.x; vs[row * 65 + c4 + 1] = vv.y;
            vs[row * 65 + c4 + 2] = vv.z; vs[row * 65 + c4 + 3] = vv.w;
        }
        __syncthreads();

        float tmax = -1e30f;
        for (int s = 0; s < 64; s++) {
            float sc;
            if (s0 + s > r) {
                sc = -1e30f;
            } else {
                sc = 0.f;
#pragma unroll
                for (int d = 0; d < 64; d++) sc += qreg[d] * ks[s * 65 + d];
            }
            scs[tid * 65 + s] = sc;
            tmax = fmaxf(tmax, sc);
        }

        float nm = fmaxf(m, tmax);
        float cf = __expf(m - nm);
        l *= cf;
#pragma unroll
        for (int d = 0; d < 64; d++) acc[d] *= cf;

        for (int s = 0; s < 64; s++) {
            float p = __expf(scs[tid * 65 + s] - nm);
            l += p;
#pragma unroll
            for (int d = 0; d < 64; d++) acc[d] += p * vs[s * 65 + d];
        }
        m = nm;
        __syncthreads();
    }

    float inv = 1.f / l;
    float* op = o + ((size_t)(n * SEQ + r)) * DM + h * HDIM;
#pragma unroll
    for (int d0 = 0; d0 < 64; d0 += 4) {
        float4 t;
        t.x = acc[d0 + 0] * inv; t.y = acc[d0 + 1] * inv;
        t.z = acc[d0 + 2] * inv; t.w = acc[d0 + 3] * inv;
        *(float4*)(op + d0) = t;
    }
}

// ---------------- residual + LayerNorm: x += LN(o)*g + b --------------------
__global__ void __launch_bounds__(256)
ln_residual(float* __restrict__ x, const float* __restrict__ o,
            const float* __restrict__ g, const float* __restrict__ b)
{
    __shared__ float red[256];
    __shared__ float s_mean, s_rstd;
    int row = blockIdx.x;
    int tid = threadIdx.x;
    const float* orow = o + (size_t)row * DM;
    float*       xrow = x + (size_t)row * DM;

    float s = 0.f;
    for (int d = tid; d < DM; d += 256) s += orow[d];
    red[tid] = s; __syncthreads();
    for (int off = 128; off > 0; off >>= 1) {
        if (tid < off) red[tid] += red[tid + off];
        __syncthreads();
    }
    if (tid == 0) s_mean = red[0] * (1.f / DM);
    __syncthreads();
    float mean = s_mean;

    float vv = 0.f;
    for (int d = tid; d < DM; d += 256) { float t = orow[d] - mean; vv += t * t; }
    red[tid] = vv; __syncthreads();
    for (int off = 128; off > 0; off >>= 1) {
        if (tid < off) red[tid] += red[tid + off];
        __syncthreads();
    }
    if (tid == 0) s_rstd = rsqrtf(red[0] * (1.f / DM) + 1e-5f);
    __syncthreads();
    float rstd = s_rstd;

    for (int d = tid; d < DM; d += 256)
        xrow[d] += (orow[d] - mean) * rstd * g[d] + b[d];
}

// ---------------- launch ----------------------------------------------------
extern "C" void kernel_launch(void* const* d_in, const int* in_sizes, int n_in,
                              void* d_out, int out_size)
{
    const int*   tokens = (const int*)  d_in[0];
    const float* emb    = (const float*)d_in[1];
    const float* pe     = (const float*)d_in[2];
    const float* Wq     = (const float*)d_in[3];
    const float* bq     = (const float*)d_in[4];
    const float* Wk     = (const float*)d_in[5];
    const float* bk     = (const float*)d_in[6];
    const float* Wv     = (const float*)d_in[7];
    const float* bv     = (const float*)d_in[8];
    const float* Wo     = (const float*)d_in[9];
    const float* bo     = (const float*)d_in[10];
    const float* g1     = (const float*)d_in[11];
    const float* be1    = (const float*)d_in[12];
    const float* W1     = (const float*)d_in[13];
    const float* b1     = (const float*)d_in[14];
    const float* W2     = (const float*)d_in[15];
    const float* b2     = (const float*)d_in[16];
    const float* g2     = (const float*)d_in[17];
    const float* be2    = (const float*)d_in[18];
    const float* Wfc    = (const float*)d_in[19];
    const float* bfc    = (const float*)d_in[20];
    float* out = (float*)d_out;

    float *x, *t0, *t1, *t2, *t3, *f1;
    cudaGetSymbolAddress((void**)&x,  g_x);
    cudaGetSymbolAddress((void**)&t0, g_t0);
    cudaGetSymbolAddress((void**)&t1, g_t1);
    cudaGetSymbolAddress((void**)&t2, g_t2);
    cudaGetSymbolAddress((void**)&t3, g_t3);
    cudaGetSymbolAddress((void**)&f1, g_f1);

    cudaFuncSetAttribute(attn_kernel,
                         cudaFuncAttributeMaxDynamicSharedMemorySize, ATTN_SMEM);
    cudaFuncSetAttribute(hgemm<false>,
                         cudaFuncAttributeMaxDynamicSharedMemorySize, GEMM_SMEM);
    cudaFuncSetAttribute(hgemm<true>,
                         cudaFuncAttributeMaxDynamicSharedMemorySize, GEMM_SMEM);

    embed_kernel<<<(MROWS * DM + 255) / 256, 256>>>(tokens, emb, pe, x);

    dim3 gDD(MROWS / 128, DM / 128);    // (16, 8)
    dim3 gDF(MROWS / 128, DFF / 128);   // (16, 32)
    dim3 gAttn(SEQ / 128, NH, BATCH);

    for (int l = 0; l < NL; l++) {
        const float* wq = Wq + (size_t)l * DM * DM;
        const float* wk = Wk + (size_t)l * DM * DM;
        const float* wv = Wv + (size_t)l * DM * DM;
        const float* wo = Wo + (size_t)l * DM * DM;
        const float* w1 = W1 + (size_t)l * DM * DFF;
        const float* w2 = W2 + (size_t)l * DFF * DM;

        hgemm<false><<<gDD, 256, GEMM_SMEM>>>(x, wq, bq + l * DM, t0, DM, DM);
        hgemm<false><<<gDD, 256, GEMM_SMEM>>>(x, wk, bk + l * DM, t1, DM, DM);
        hgemm<false><<<gDD, 256, GEMM_SMEM>>>(x, wv, bv + l * DM, t2, DM, DM);

        attn_kernel<<<gAttn, 128, ATTN_SMEM>>>(t0, t1, t2, t3);

        hgemm<false><<<gDD, 256, GEMM_SMEM>>>(t3, wo, bo + l * DM, t0, DM, DM);
        ln_residual<<<MROWS, 256>>>(x, t0, g1 + l * DM, be1 + l * DM);

        hgemm<true ><<<gDF, 256, GEMM_SMEM>>>(x,  w1, b1 + l * DFF, f1, DFF, DM);
        hgemm<false><<<gDD, 256, GEMM_SMEM>>>(f1, w2, b2 + l * DM,  t0, DM, DFF);
        ln_residual<<<MROWS, 256>>>(x, t0, g2 + l * DM, be2 + l * DM);
    }

    dim3 gV(MROWS / 128, VOCAB / 128);  // (16, 250)
    hgemm<false><<<gV, 256, GEMM_SMEM>>>(x, Wfc, bfc, out, VOCAB, DM);
}

// round 10
// speedup vs baseline: 2.1153x; 1.2561x over previous
#include <cuda_runtime.h>
#include <cuda_bf16.h>
#include <cuda_fp16.h>
#include <math.h>
#include <stdint.h>

#define BATCH 4
#define SEQ   512
#define DM    1024
#define NH    16
#define NL    8
#define VOCAB 32000
#define HDIM  64
#define DFF   4096
#define MROWS (BATCH*SEQ)

// fp32 scratch
__device__ float g_x [MROWS*DM];
__device__ float g_t0[MROWS*DM];
__device__ float g_t1[MROWS*DM];
__device__ float g_t2[MROWS*DM];
__device__ float g_t3[MROWS*DM];
__device__ float g_f1[MROWS*DFF];
// fp16 weights (converted per launch) + fp16 activations
__device__ __half g_hWq[NL*DM*DM];
__device__ __half g_hWk[NL*DM*DM];
__device__ __half g_hWv[NL*DM*DM];
__device__ __half g_hWo[NL*DM*DM];
__device__ __half g_hW1[NL*DM*DFF];
__device__ __half g_hW2[NL*DFF*DM];
__device__ __half g_hWfc[DM*VOCAB];
__device__ __half g_hx [MROWS*DM];
__device__ __half g_ht3[MROWS*DM];
__device__ __half g_hf1[MROWS*DFF];

__device__ __forceinline__ uint32_t h2pk(float x, float y){
    __half2 h = __floats2half2_rn(x, y);
    return *(uint32_t*)&h;
}

__global__ void cvt_f2h(const float* __restrict__ s, __half* __restrict__ d, int n){
    int i = (blockIdx.x * blockDim.x + threadIdx.x) * 4;
    if (i >= n) return;
    float4 v = *(const float4*)(s + i);
    uint2 h = make_uint2(h2pk(v.x, v.y), h2pk(v.z, v.w));
    *(uint2*)(d + i) = h;
}

__global__ void embed_kernel(const int* __restrict__ tokens,
                             const float* __restrict__ emb,
                             const float* __restrict__ pe,
                             float* __restrict__ x)
{
    int idx = blockIdx.x * blockDim.x + threadIdx.x;
    if (idx >= MROWS * DM) return;
    int d  = idx % DM;
    int nt = idx / DM;
    int n  = nt / SEQ;
    int tok = tokens[nt];
    x[idx] = emb[(size_t)tok * DM + d] + pe[(size_t)n * DM + d];
}

// ===== fp16 cp.async GEMM: C(MxN)=A@B+bias (opt ReLU), fp32 accum ============
// Tile 128x128, BK=64, 3-buffer cp.async ring (2 in flight), 256 thr, 8 warps
// 2(M)x4(N), warp tile 64x32. A smem [128][72]h, B smem [64][136]h.
#define PADA_H 72
#define PADB_H 136
#define A_BYTES (128*PADA_H*2)        // 18432
#define B_BYTES (64*PADB_H*2)         // 17408
#define STG_BYTES (A_BYTES + B_BYTES) // 35840
#define GEMM_SMEM (3*STG_BYTES)       // 107520

__device__ __forceinline__ uint32_t cvta_smem(const void* p){
    uint32_t a;
    asm("{ .reg .u64 t; cvta.to.shared.u64 t, %1; cvt.u32.u64 %0, t; }" : "=r"(a) : "l"(p));
    return a;
}
__device__ __forceinline__ void cpa16(uint32_t daddr, const void* g){
    asm volatile("cp.async.cg.shared.global [%0], [%1], 16;" :: "r"(daddr), "l"(g));
}
__device__ __forceinline__ void cp_commit(){ asm volatile("cp.async.commit_group;"); }
__device__ __forceinline__ void cp_wait1(){ asm volatile("cp.async.wait_group 1;"); }
__device__ __forceinline__ void cp_wait0(){ asm volatile("cp.async.wait_group 0;"); }
__device__ __forceinline__ void ldm4(uint32_t* r, uint32_t addr){
    asm volatile("ldmatrix.sync.aligned.m8n8.x4.shared.b16 {%0,%1,%2,%3}, [%4];"
                 : "=r"(r[0]), "=r"(r[1]), "=r"(r[2]), "=r"(r[3]) : "r"(addr));
}
__device__ __forceinline__ void ldm4t(uint32_t* r, uint32_t addr){
    asm volatile("ldmatrix.sync.aligned.m8n8.x4.trans.shared.b16 {%0,%1,%2,%3}, [%4];"
                 : "=r"(r[0]), "=r"(r[1]), "=r"(r[2]), "=r"(r[3]) : "r"(addr));
}
__device__ __forceinline__ void mma_f16(float* c, const uint32_t* a, const uint32_t* b){
    asm volatile(
        "mma.sync.aligned.m16n8k16.row.col.f32.f16.f16.f32 "
        "{%0,%1,%2,%3}, {%4,%5,%6,%7}, {%8,%9}, {%0,%1,%2,%3};"
        : "+f"(c[0]), "+f"(c[1]), "+f"(c[2]), "+f"(c[3])
        : "r"(a[0]), "r"(a[1]), "r"(a[2]), "r"(a[3]), "r"(b[0]), "r"(b[1]));
}

template<bool RELU>
__global__ void __launch_bounds__(256, 2)
hgemm(const __half* __restrict__ A, const __half* __restrict__ B,
      const float* __restrict__ bias, float* __restrict__ C,
      int Nn, int K)
{
    extern __shared__ __half smem[];
    const int tid = threadIdx.x, lane = tid & 31, warp = tid >> 5;
    const int warp_m = warp & 1, warp_n = warp >> 1;
    const int mbase = blockIdx.x * 128, nbase = blockIdx.y * 128;

    const __half* Ag = A + (size_t)mbase * K;
    const __half* Bg = B + nbase;
    const int NC = K >> 6;

    const uint32_t smem_u = cvta_smem(smem);

    // cp.async mappings: A 1024 x16B chunks, B 1024 x16B chunks per stage
    const int a_row = tid >> 3, a_c8 = tid & 7;     // + p*32 rows
    const int b_row = tid >> 4, b_c16 = tid & 15;   // + p*16 rows

    // fragment address offsets (within a stage)
    const int g = lane >> 2, tig = lane & 3;
    const int sel = lane >> 3, l7 = lane & 7;
    uint32_t a_rel[4], b_rel[2];
#pragma unroll
    for (int mt = 0; mt < 4; mt++){
        int row = warp_m * 64 + mt * 16 + (sel & 1) * 8 + l7;
        a_rel[mt] = (uint32_t)(row * (PADA_H*2)) + (uint32_t)((sel >> 1) * 16);
    }
#pragma unroll
    for (int np2 = 0; np2 < 2; np2++){
        int krow = (sel & 1) * 8 + l7;
        int ncol = warp_n * 32 + np2 * 16 + (sel >> 1) * 8;
        b_rel[np2] = (uint32_t)A_BYTES + (uint32_t)(krow * (PADB_H*2)) + (uint32_t)(ncol * 2);
    }

    float acc[4][4][4];
#pragma unroll
    for (int mt = 0; mt < 4; mt++)
#pragma unroll
        for (int np = 0; np < 4; np++)
#pragma unroll
            for (int i = 0; i < 4; i++) acc[mt][np][i] = 0.f;

    auto issue_stage = [&](int chunk, int buf){
        uint32_t base = smem_u + (uint32_t)buf * STG_BYTES;
        const __half* As = Ag + (size_t)chunk * 64;
#pragma unroll
        for (int p = 0; p < 4; p++){
            int row = a_row + p * 32;
            cpa16(base + row * (PADA_H*2) + a_c8 * 16,
                  As + (size_t)row * K + a_c8 * 8);
        }
        const __half* Bs = Bg + (size_t)(chunk * 64) * Nn;
#pragma unroll
        for (int p = 0; p < 4; p++){
            int row = b_row + p * 16;
            cpa16(base + A_BYTES + row * (PADB_H*2) + b_c16 * 16,
                  Bs + (size_t)row * Nn + b_c16 * 8);
        }
        cp_commit();
    };

    issue_stage(0, 0);
    if (NC > 1) issue_stage(1, 1);

    int buf = 0;
    for (int c = 0; c < NC; c++){
        if (c + 1 < NC) cp_wait1(); else cp_wait0();
        __syncthreads();
        if (c + 2 < NC){
            int nb = buf + 2; if (nb >= 3) nb -= 3;
            issue_stage(c + 2, nb);
        }

        const uint32_t sbase = smem_u + (uint32_t)buf * STG_BYTES;
#pragma unroll
        for (int ks = 0; ks < 4; ks++){
            uint32_t af[16], bf[8];
#pragma unroll
            for (int mt = 0; mt < 4; mt++)
                ldm4(&af[4*mt], sbase + a_rel[mt] + ks * 32);
#pragma unroll
            for (int np2 = 0; np2 < 2; np2++)
                ldm4t(&bf[4*np2], sbase + b_rel[np2] + ks * 16 * (PADB_H*2));
#pragma unroll
            for (int mt = 0; mt < 4; mt++)
#pragma unroll
                for (int np = 0; np < 4; np++)
                    mma_f16(acc[mt][np], &af[4*mt], &bf[2*np]);
        }

        if (++buf == 3) buf = 0;
    }

    // epilogue
#pragma unroll
    for (int mt = 0; mt < 4; mt++){
        int row0 = mbase + warp_m * 64 + mt * 16 + g;
#pragma unroll
        for (int np = 0; np < 4; np++){
            int col = nbase + warp_n * 32 + np * 8 + 2 * tig;
            float b0 = bias[col], b1 = bias[col + 1];
            float2 v0 = make_float2(acc[mt][np][0] + b0, acc[mt][np][1] + b1);
            float2 v1 = make_float2(acc[mt][np][2] + b0, acc[mt][np][3] + b1);
            if (RELU){
                v0.x = fmaxf(v0.x, 0.f); v0.y = fmaxf(v0.y, 0.f);
                v1.x = fmaxf(v1.x, 0.f); v1.y = fmaxf(v1.y, 0.f);
            }
            *(float2*)&C[(size_t)row0 * Nn + col]       = v0;
            *(float2*)&C[(size_t)(row0 + 8) * Nn + col] = v1;
        }
    }
}

// ---------------- causal attention (flash-style, fp32) ----------------------
#define ATTN_SMEM ((128*65 + 64*65 + 64*65 + 128*65) * 4)

__global__ void __launch_bounds__(128)
attn_kernel(const float* __restrict__ q, const float* __restrict__ k,
            const float* __restrict__ v, float* __restrict__ o)
{
    extern __shared__ float sm[];
    float* qs  = sm;
    float* ks  = qs + 128 * 65;
    float* vs  = ks + 64 * 65;
    float* scs = vs + 64 * 65;

    int n  = blockIdx.z;
    int h  = blockIdx.y;
    int qt = blockIdx.x;
    int tid = threadIdx.x;
    int r = qt * 128 + tid;

    for (int i = tid; i < 128 * 16; i += 128) {
        int row = i >> 4, c4 = (i & 15) * 4;
        float4 t = *(const float4*)(q + ((size_t)(n * SEQ + qt * 128 + row)) * DM + h * HDIM + c4);
        qs[row * 65 + c4 + 0] = t.x; qs[row * 65 + c4 + 1] = t.y;
        qs[row * 65 + c4 + 2] = t.z; qs[row * 65 + c4 + 3] = t.w;
    }
    __syncthreads();

    float qreg[64];
#pragma unroll
    for (int d = 0; d < 64; d++) qreg[d] = qs[tid * 65 + d] * 0.125f;

    float m = -1e30f, l = 0.f;
    float acc[64];
#pragma unroll
    for (int d = 0; d < 64; d++) acc[d] = 0.f;

    int smax = qt * 128 + 127;
    for (int s0 = 0; s0 <= smax; s0 += 64) {
        for (int i = tid; i < 64 * 16; i += 128) {
            int row = i >> 4, c4 = (i & 15) * 4;
            size_t base = ((size_t)(n * SEQ + s0 + row)) * DM + h * HDIM + c4;
            float4 kk = *(const float4*)(k + base);
            ks[row * 65 + c4 + 0] = kk.x; ks[row * 65 + c4 + 1] = kk.y;
            ks[row * 65 + c4 + 2] = kk.z; ks[row * 65 + c4 + 3] = kk.w;
            float4 vv = *(const float4*)(v + base);
            vs[row * 65 + c4 + 0] = vv.x; vs[row * 65 + c4 + 1] = vv.y;
            vs[row * 65 + c4 + 2] = vv.z; vs[row * 65 + c4 + 3] = vv.w;
        }
        __syncthreads();

        float tmax = -1e30f;
        for (int s = 0; s < 64; s++) {
            float sc;
            if (s0 + s > r) {
                sc = -1e30f;
            } else {
                sc = 0.f;
#pragma unroll
                for (int d = 0; d < 64; d++) sc += qreg[d] * ks[s * 65 + d];
            }
            scs[tid * 65 + s] = sc;
            tmax = fmaxf(tmax, sc);
        }

        float nm = fmaxf(m, tmax);
        float cf = __expf(m - nm);
        l *= cf;
#pragma unroll
        for (int d = 0; d < 64; d++) acc[d] *= cf;

        for (int s = 0; s < 64; s++) {
            float p = __expf(scs[tid * 65 + s] - nm);
            l += p;
#pragma unroll
            for (int d = 0; d < 64; d++) acc[d] += p * vs[s * 65 + d];
        }
        m = nm;
        __syncthreads();
    }

    float inv = 1.f / l;
    float* op = o + ((size_t)(n * SEQ + r)) * DM + h * HDIM;
#pragma unroll
    for (int d0 = 0; d0 < 64; d0 += 4) {
        float4 t;
        t.x = acc[d0 + 0] * inv; t.y = acc[d0 + 1] * inv;
        t.z = acc[d0 + 2] * inv; t.w = acc[d0 + 3] * inv;
        *(float4*)(op + d0) = t;
    }
}

// ---------------- residual + LayerNorm: x += LN(o)*g + b --------------------
__global__ void __launch_bounds__(256)
ln_residual(float* __restrict__ x, const float* __restrict__ o,
            const float* __restrict__ g, const float* __restrict__ b)
{
    __shared__ float red[256];
    __shared__ float s_mean, s_rstd;
    int row = blockIdx.x;
    int tid = threadIdx.x;
    const float* orow = o + (size_t)row * DM;
    float*       xrow = x + (size_t)row * DM;

    float s = 0.f;
    for (int d = tid; d < DM; d += 256) s += orow[d];
    red[tid] = s; __syncthreads();
    for (int off = 128; off > 0; off >>= 1) {
        if (tid < off) red[tid] += red[tid + off];
        __syncthreads();
    }
    if (tid == 0) s_mean = red[0] * (1.f / DM);
    __syncthreads();
    float mean = s_mean;

    float vv = 0.f;
    for (int d = tid; d < DM; d += 256) { float t = orow[d] - mean; vv += t * t; }
    red[tid] = vv; __syncthreads();
    for (int off = 128; off > 0; off >>= 1) {
        if (tid < off) red[tid] += red[tid + off];
        __syncthreads();
    }
    if (tid == 0) s_rstd = rsqrtf(red[0] * (1.f / DM) + 1e-5f);
    __syncthreads();
    float rstd = s_rstd;

    for (int d = tid; d < DM; d += 256)
        xrow[d] += (orow[d] - mean) * rstd * g[d] + b[d];
}

// ---------------- launch ----------------------------------------------------
extern "C" void kernel_launch(void* const* d_in, const int* in_sizes, int n_in,
                              void* d_out, int out_size)
{
    const int*   tokens = (const int*)  d_in[0];
    const float* emb    = (const float*)d_in[1];
    const float* pe     = (const float*)d_in[2];
    const float* Wq     = (const float*)d_in[3];
    const float* bq     = (const float*)d_in[4];
    const float* Wk     = (const float*)d_in[5];
    const float* bk     = (const float*)d_in[6];
    const float* Wv     = (const float*)d_in[7];
    const float* bv     = (const float*)d_in[8];
    const float* Wo     = (const float*)d_in[9];
    const float* bo     = (const float*)d_in[10];
    const float* g1     = (const float*)d_in[11];
    const float* be1    = (const float*)d_in[12];
    const float* W1     = (const float*)d_in[13];
    const float* b1     = (const float*)d_in[14];
    const float* W2     = (const float*)d_in[15];
    const float* b2     = (const float*)d_in[16];
    const float* g2     = (const float*)d_in[17];
    const float* be2    = (const float*)d_in[18];
    const float* Wfc    = (const float*)d_in[19];
    const float* bfc    = (const float*)d_in[20];
    float* out = (float*)d_out;

    float *x, *t0, *t1, *t2, *t3, *f1;
    __half *hWq, *hWk, *hWv, *hWo, *hW1, *hW2, *hWfc, *hx, *ht3, *hf1;
    cudaGetSymbolAddress((void**)&x,  g_x);
    cudaGetSymbolAddress((void**)&t0, g_t0);
    cudaGetSymbolAddress((void**)&t1, g_t1);
    cudaGetSymbolAddress((void**)&t2, g_t2);
    cudaGetSymbolAddress((void**)&t3, g_t3);
    cudaGetSymbolAddress((void**)&f1, g_f1);
    cudaGetSymbolAddress((void**)&hWq, g_hWq);
    cudaGetSymbolAddress((void**)&hWk, g_hWk);
    cudaGetSymbolAddress((void**)&hWv, g_hWv);
    cudaGetSymbolAddress((void**)&hWo, g_hWo);
    cudaGetSymbolAddress((void**)&hW1, g_hW1);
    cudaGetSymbolAddress((void**)&hW2, g_hW2);
    cudaGetSymbolAddress((void**)&hWfc, g_hWfc);
    cudaGetSymbolAddress((void**)&hx,  g_hx);
    cudaGetSymbolAddress((void**)&ht3, g_ht3);
    cudaGetSymbolAddress((void**)&hf1, g_hf1);

    cudaFuncSetAttribute(attn_kernel,
                         cudaFuncAttributeMaxDynamicSharedMemorySize, ATTN_SMEM);
    cudaFuncSetAttribute(hgemm<false>,
                         cudaFuncAttributeMaxDynamicSharedMemorySize, GEMM_SMEM);
    cudaFuncSetAttribute(hgemm<true>,
                         cudaFuncAttributeMaxDynamicSharedMemorySize, GEMM_SMEM);

    // weights -> fp16 (rn; identical rounding to prior in-kernel cvt)
    const int CB = 256;
    cvt_f2h<<<(NL*DM*DM/4 + CB-1)/CB, CB>>>(Wq, hWq, NL*DM*DM);
    cvt_f2h<<<(NL*DM*DM/4 + CB-1)/CB, CB>>>(Wk, hWk, NL*DM*DM);
    cvt_f2h<<<(NL*DM*DM/4 + CB-1)/CB, CB>>>(Wv, hWv, NL*DM*DM);
    cvt_f2h<<<(NL*DM*DM/4 + CB-1)/CB, CB>>>(Wo, hWo, NL*DM*DM);
    cvt_f2h<<<(NL*DM*DFF/4 + CB-1)/CB, CB>>>(W1, hW1, NL*DM*DFF);
    cvt_f2h<<<(NL*DFF*DM/4 + CB-1)/CB, CB>>>(W2, hW2, NL*DFF*DM);
    cvt_f2h<<<(DM*VOCAB/4 + CB-1)/CB, CB>>>(Wfc, hWfc, DM*VOCAB);

    embed_kernel<<<(MROWS * DM + 255) / 256, 256>>>(tokens, emb, pe, x);

    dim3 gDD(MROWS / 128, DM / 128);    // (16, 8)
    dim3 gDF(MROWS / 128, DFF / 128);   // (16, 32)
    dim3 gAttn(SEQ / 128, NH, BATCH);

    for (int l = 0; l < NL; l++) {
        const __half* wq = hWq + (size_t)l * DM * DM;
        const __half* wk = hWk + (size_t)l * DM * DM;
        const __half* wv = hWv + (size_t)l * DM * DM;
        const __half* wo = hWo + (size_t)l * DM * DM;
        const __half* w1 = hW1 + (size_t)l * DM * DFF;
        const __half* w2 = hW2 + (size_t)l * DFF * DM;

        cvt_f2h<<<(MROWS*DM/4 + CB-1)/CB, CB>>>(x, hx, MROWS*DM);
        hgemm<false><<<gDD, 256, GEMM_SMEM>>>(hx, wq, bq + l * DM, t0, DM, DM);
        hgemm<false><<<gDD, 256, GEMM_SMEM>>>(hx, wk, bk + l * DM, t1, DM, DM);
        hgemm<false><<<gDD, 256, GEMM_SMEM>>>(hx, wv, bv + l * DM, t2, DM, DM);

        attn_kernel<<<gAttn, 128, ATTN_SMEM>>>(t0, t1, t2, t3);

        cvt_f2h<<<(MROWS*DM/4 + CB-1)/CB, CB>>>(t3, ht3, MROWS*DM);
        hgemm<false><<<gDD, 256, GEMM_SMEM>>>(ht3, wo, bo + l * DM, t0, DM, DM);
        ln_residual<<<MROWS, 256>>>(x, t0, g1 + l * DM, be1 + l * DM);

        cvt_f2h<<<(MROWS*DM/4 + CB-1)/CB, CB>>>(x, hx, MROWS*DM);
        hgemm<true ><<<gDF, 256, GEMM_SMEM>>>(hx, w1, b1 + l * DFF, f1, DFF, DM);
        cvt_f2h<<<(MROWS*DFF/4 + CB-1)/CB, CB>>>(f1, hf1, MROWS*DFF);
        hgemm<false><<<gDD, 256, GEMM_SMEM>>>(hf1, w2, b2 + l * DM, t0, DM, DFF);
        ln_residual<<<MROWS, 256>>>(x, t0, g2 + l * DM, be2 + l * DM);
    }

    cvt_f2h<<<(MROWS*DM/4 + CB-1)/CB, CB>>>(x, hx, MROWS*DM);
    dim3 gV(MROWS / 128, VOCAB / 128);  // (16, 250)
    hgemm<false><<<gV, 256, GEMM_SMEM>>>(hx, hWfc, bfc, out, VOCAB, DM);
}

// round 11
// speedup vs baseline: 2.2034x; 1.0417x over previous
#include <cuda_runtime.h>
#include <cuda_bf16.h>
#include <cuda_fp16.h>
#include <math.h>
#include <stdint.h>

#define BATCH 4
#define SEQ   512
#define DM    1024
#define NH    16
#define NL    8
#define VOCAB 32000
#define HDIM  64
#define DFF   4096
#define MROWS (BATCH*SEQ)
#define DM3   (3*DM)

// fp32 scratch
__device__ float g_x  [MROWS*DM];
__device__ float g_t0 [MROWS*DM];
__device__ float g_t3 [MROWS*DM];
__device__ float g_qkv[MROWS*DM3];
// fp16 weights / activations
__device__ __half g_hWqkv[NL*DM*DM3];
__device__ __half g_hWo[NL*DM*DM];
__device__ __half g_hW1[NL*DM*DFF];
__device__ __half g_hW2[NL*DFF*DM];
__device__ __half g_hWfc[DM*VOCAB];
__device__ __half g_hx [MROWS*DM];
__device__ __half g_ht3[MROWS*DM];
__device__ __half g_hf1[MROWS*DFF];
__device__ float  g_bqkv[NL*DM3];

__device__ __forceinline__ uint32_t h2pk(float x, float y){
    __half2 h = __floats2half2_rn(x, y);
    return *(uint32_t*)&h;
}

__global__ void cvt_f2h(const float* __restrict__ s, __half* __restrict__ d, int n){
    int i = (blockIdx.x * blockDim.x + threadIdx.x) * 4;
    if (i >= n) return;
    float4 v = *(const float4*)(s + i);
    uint2 h = make_uint2(h2pk(v.x, v.y), h2pk(v.z, v.w));
    *(uint2*)(d + i) = h;
}

// pack Wq|Wk|Wv -> [L][D][3D] fp16
__global__ void pack_qkv_w(const float* __restrict__ Wq, const float* __restrict__ Wk,
                           const float* __restrict__ Wv, __half* __restrict__ d)
{
    long long i = ((long long)blockIdx.x * blockDim.x + threadIdx.x) * 4;
    if (i >= (long long)NL * DM * DM3) return;
    int l = (int)(i / ((long long)DM * DM3));
    long long rem = i % ((long long)DM * DM3);
    int k = (int)(rem / DM3);
    int c = (int)(rem % DM3);
    const float* src = (c < DM) ? Wq : ((c < 2*DM) ? Wk : Wv);
    int sc = c % DM;
    float4 v = *(const float4*)(src + (size_t)l * DM * DM + (size_t)k * DM + sc);
    uint2 h = make_uint2(h2pk(v.x, v.y), h2pk(v.z, v.w));
    *(uint2*)(d + i) = h;
}
__global__ void pack_qkv_b(const float* __restrict__ bq, const float* __restrict__ bk,
                           const float* __restrict__ bv, float* __restrict__ d)
{
    int i = blockIdx.x * blockDim.x + threadIdx.x;
    if (i >= NL * DM3) return;
    int l = i / DM3, c = i % DM3;
    const float* src = (c < DM) ? bq : ((c < 2*DM) ? bk : bv);
    d[i] = src[(size_t)l * DM + (c % DM)];
}

__global__ void embed_kernel(const int* __restrict__ tokens,
                             const float* __restrict__ emb,
                             const float* __restrict__ pe,
                             float* __restrict__ x, __half* __restrict__ hx)
{
    int idx = blockIdx.x * blockDim.x + threadIdx.x;
    if (idx >= MROWS * DM) return;
    int d  = idx % DM;
    int nt = idx / DM;
    int n  = nt / SEQ;
    int tok = tokens[nt];
    float v = emb[(size_t)tok * DM + d] + pe[(size_t)n * DM + d];
    x[idx] = v;
    hx[idx] = __float2half_rn(v);
}

// ===== fp16 cp.async GEMM: C=A@B+bias (opt ReLU), fp32 accum =================
#define PADA_H 72
#define PADB_H 136
#define A_BYTES (128*PADA_H*2)
#define B_BYTES (64*PADB_H*2)
#define STG_BYTES (A_BYTES + B_BYTES)
#define GEMM_SMEM (3*STG_BYTES)

__device__ __forceinline__ uint32_t cvta_smem(const void* p){
    uint32_t a;
    asm("{ .reg .u64 t; cvta.to.shared.u64 t, %1; cvt.u32.u64 %0, t; }" : "=r"(a) : "l"(p));
    return a;
}
__device__ __forceinline__ void cpa16(uint32_t daddr, const void* g){
    asm volatile("cp.async.cg.shared.global [%0], [%1], 16;" :: "r"(daddr), "l"(g));
}
__device__ __forceinline__ void cp_commit(){ asm volatile("cp.async.commit_group;"); }
__device__ __forceinline__ void cp_wait1(){ asm volatile("cp.async.wait_group 1;"); }
__device__ __forceinline__ void cp_wait0(){ asm volatile("cp.async.wait_group 0;"); }
__device__ __forceinline__ void ldm4(uint32_t* r, uint32_t addr){
    asm volatile("ldmatrix.sync.aligned.m8n8.x4.shared.b16 {%0,%1,%2,%3}, [%4];"
                 : "=r"(r[0]), "=r"(r[1]), "=r"(r[2]), "=r"(r[3]) : "r"(addr));
}
__device__ __forceinline__ void ldm4t(uint32_t* r, uint32_t addr){
    asm volatile("ldmatrix.sync.aligned.m8n8.x4.trans.shared.b16 {%0,%1,%2,%3}, [%4];"
                 : "=r"(r[0]), "=r"(r[1]), "=r"(r[2]), "=r"(r[3]) : "r"(addr));
}
__device__ __forceinline__ void mma_f16(float* c, const uint32_t* a, const uint32_t* b){
    asm volatile(
        "mma.sync.aligned.m16n8k16.row.col.f32.f16.f16.f32 "
        "{%0,%1,%2,%3}, {%4,%5,%6,%7}, {%8,%9}, {%0,%1,%2,%3};"
        : "+f"(c[0]), "+f"(c[1]), "+f"(c[2]), "+f"(c[3])
        : "r"(a[0]), "r"(a[1]), "r"(a[2]), "r"(a[3]), "r"(b[0]), "r"(b[1]));
}

template<bool RELU, bool OUTH>
__global__ void __launch_bounds__(256, 2)
hgemm(const __half* __restrict__ A, const __half* __restrict__ B,
      const float* __restrict__ bias, void* __restrict__ Cout,
      int Nn, int K)
{
    extern __shared__ __half smem[];
    const int tid = threadIdx.x, lane = tid & 31, warp = tid >> 5;
    const int warp_m = warp & 1, warp_n = warp >> 1;
    const int mbase = blockIdx.x * 128, nbase = blockIdx.y * 128;

    const __half* Ag = A + (size_t)mbase * K;
    const __half* Bg = B + nbase;
    const int NC = K >> 6;

    const uint32_t smem_u = cvta_smem(smem);
    const int a_row = tid >> 3, a_c8 = tid & 7;
    const int b_row = tid >> 4, b_c16 = tid & 15;

    const int g = lane >> 2, tig = lane & 3;
    const int sel = lane >> 3, l7 = lane & 7;
    uint32_t a_rel[4], b_rel[2];
#pragma unroll
    for (int mt = 0; mt < 4; mt++){
        int row = warp_m * 64 + mt * 16 + (sel & 1) * 8 + l7;
        a_rel[mt] = (uint32_t)(row * (PADA_H*2)) + (uint32_t)((sel >> 1) * 16);
    }
#pragma unroll
    for (int np2 = 0; np2 < 2; np2++){
        int krow = (sel & 1) * 8 + l7;
        int ncol = warp_n * 32 + np2 * 16 + (sel >> 1) * 8;
        b_rel[np2] = (uint32_t)A_BYTES + (uint32_t)(krow * (PADB_H*2)) + (uint32_t)(ncol * 2);
    }

    float acc[4][4][4];
#pragma unroll
    for (int mt = 0; mt < 4; mt++)
#pragma unroll
        for (int np = 0; np < 4; np++)
#pragma unroll
            for (int i = 0; i < 4; i++) acc[mt][np][i] = 0.f;

    auto issue_stage = [&](int chunk, int buf){
        uint32_t base = smem_u + (uint32_t)buf * STG_BYTES;
        const __half* As = Ag + (size_t)chunk * 64;
#pragma unroll
        for (int p = 0; p < 4; p++){
            int row = a_row + p * 32;
            cpa16(base + row * (PADA_H*2) + a_c8 * 16,
                  As + (size_t)row * K + a_c8 * 8);
        }
        const __half* Bs = Bg + (size_t)(chunk * 64) * Nn;
#pragma unroll
        for (int p = 0; p < 4; p++){
            int row = b_row + p * 16;
            cpa16(base + A_BYTES + row * (PADB_H*2) + b_c16 * 16,
                  Bs + (size_t)row * Nn + b_c16 * 8);
        }
        cp_commit();
    };

    issue_stage(0, 0);
    if (NC > 1) issue_stage(1, 1);

    int buf = 0;
    for (int c = 0; c < NC; c++){
        if (c + 1 < NC) cp_wait1(); else cp_wait0();
        __syncthreads();
        if (c + 2 < NC){
            int nb = buf + 2; if (nb >= 3) nb -= 3;
            issue_stage(c + 2, nb);
        }

        const uint32_t sbase = smem_u + (uint32_t)buf * STG_BYTES;
#pragma unroll
        for (int ks = 0; ks < 4; ks++){
            uint32_t af[16], bf[8];
#pragma unroll
            for (int mt = 0; mt < 4; mt++)
                ldm4(&af[4*mt], sbase + a_rel[mt] + ks * 32);
#pragma unroll
            for (int np2 = 0; np2 < 2; np2++)
                ldm4t(&bf[4*np2], sbase + b_rel[np2] + ks * 16 * (PADB_H*2));
#pragma unroll
            for (int mt = 0; mt < 4; mt++)
#pragma unroll
                for (int np = 0; np < 4; np++)
                    mma_f16(acc[mt][np], &af[4*mt], &bf[2*np]);
        }

        if (++buf == 3) buf = 0;
    }

    // epilogue
#pragma unroll
    for (int mt = 0; mt < 4; mt++){
        int row0 = mbase + warp_m * 64 + mt * 16 + g;
#pragma unroll
        for (int np = 0; np < 4; np++){
            int col = nbase + warp_n * 32 + np * 8 + 2 * tig;
            float b0 = bias[col], b1 = bias[col + 1];
            float2 v0 = make_float2(acc[mt][np][0] + b0, acc[mt][np][1] + b1);
            float2 v1 = make_float2(acc[mt][np][2] + b0, acc[mt][np][3] + b1);
            if (RELU){
                v0.x = fmaxf(v0.x, 0.f); v0.y = fmaxf(v0.y, 0.f);
                v1.x = fmaxf(v1.x, 0.f); v1.y = fmaxf(v1.y, 0.f);
            }
            if (OUTH){
                __half* Ch = (__half*)Cout;
                *(uint32_t*)&Ch[(size_t)row0 * Nn + col]       = h2pk(v0.x, v0.y);
                *(uint32_t*)&Ch[(size_t)(row0 + 8) * Nn + col] = h2pk(v1.x, v1.y);
            } else {
                float* C = (float*)Cout;
                *(float2*)&C[(size_t)row0 * Nn + col]       = v0;
                *(float2*)&C[(size_t)(row0 + 8) * Nn + col] = v1;
            }
        }
    }
}

// ------- causal attention (flash-style, fp32); reads packed qkv --------------
#define ATTN_SMEM ((128*65 + 64*65 + 64*65 + 128*65) * 4)

__global__ void __launch_bounds__(128)
attn_kernel(const float* __restrict__ qkv, float* __restrict__ o,
            __half* __restrict__ oh)
{
    extern __shared__ float sm[];
    float* qs  = sm;
    float* ks  = qs + 128 * 65;
    float* vs  = ks + 64 * 65;
    float* scs = vs + 64 * 65;

    int n  = blockIdx.z;
    int h  = blockIdx.y;
    int qt = blockIdx.x;
    int tid = threadIdx.x;
    int r = qt * 128 + tid;

    const float* qb = qkv + h * HDIM;              // q cols
    const float* kb = qkv + DM + h * HDIM;         // k cols
    const float* vb = qkv + 2 * DM + h * HDIM;     // v cols

    for (int i = tid; i < 128 * 16; i += 128) {
        int row = i >> 4, c4 = (i & 15) * 4;
        float4 t = *(const float4*)(qb + ((size_t)(n * SEQ + qt * 128 + row)) * DM3 + c4);
        qs[row * 65 + c4 + 0] = t.x; qs[row * 65 + c4 + 1] = t.y;
        qs[row * 65 + c4 + 2] = t.z; qs[row * 65 + c4 + 3] = t.w;
    }
    __syncthreads();

    float qreg[64];
#pragma unroll
    for (int d = 0; d < 64; d++) qreg[d] = qs[tid * 65 + d] * 0.125f;

    float m = -1e30f, l = 0.f;
    float acc[64];
#pragma unroll
    for (int d = 0; d < 64; d++) acc[d] = 0.f;

    int smax = qt * 128 + 127;
    for (int s0 = 0; s0 <= smax; s0 += 64) {
        for (int i = tid; i < 64 * 16; i += 128) {
            int row = i >> 4, c4 = (i & 15) * 4;
            size_t base = ((size_t)(n * SEQ + s0 + row)) * DM3 + c4;
            float4 kk = *(const float4*)(kb + base);
            ks[row * 65 + c4 + 0] = kk.x; ks[row * 65 + c4 + 1] = kk.y;
            ks[row * 65 + c4 + 2] = kk.z; ks[row * 65 + c4 + 3] = kk.w;
            float4 vv = *(const float4*)(vb + base);
            vs[row * 65 + c4 + 0] = vv.x; vs[row * 65 + c4 + 1] = vv.y;
            vs[row * 65 + c4 + 2] = vv.z; vs[row * 65 + c4 + 3] = vv.w;
        }
        __syncthreads();

        float tmax = -1e30f;
        for (int s = 0; s < 64; s++) {
            float sc;
            if (s0 + s > r) {
                sc = -1e30f;
            } else {
                sc = 0.f;
#pragma unroll
                for (int d = 0; d < 64; d++) sc += qreg[d] * ks[s * 65 + d];
            }
            scs[tid * 65 + s] = sc;
            tmax = fmaxf(tmax, sc);
        }

        float nm = fmaxf(m, tmax);
        float cf = __expf(m - nm);
        l *= cf;
#pragma unroll
        for (int d = 0; d < 64; d++) acc[d] *= cf;

        for (int s = 0; s < 64; s++) {
            float p = __expf(scs[tid * 65 + s] - nm);
            l += p;
#pragma unroll
            for (int d = 0; d < 64; d++) acc[d] += p * vs[s * 65 + d];
        }
        m = nm;
        __syncthreads();
    }

    float inv = 1.f / l;
    size_t obase = ((size_t)(n * SEQ + r)) * DM + h * HDIM;
#pragma unroll
    for (int d0 = 0; d0 < 64; d0 += 4) {
        float4 t;
        t.x = acc[d0 + 0] * inv; t.y = acc[d0 + 1] * inv;
        t.z = acc[d0 + 2] * inv; t.w = acc[d0 + 3] * inv;
        *(float4*)(o + obase + d0) = t;
        uint2 hh = make_uint2(h2pk(t.x, t.y), h2pk(t.z, t.w));
        *(uint2*)(oh + obase + d0) = hh;
    }
}

// ---- residual + LayerNorm: x += LN(o)*g + b ; also emit fp16 x --------------
__global__ void __launch_bounds__(256)
ln_residual(float* __restrict__ x, const float* __restrict__ o,
            const float* __restrict__ g, const float* __restrict__ b,
            __half* __restrict__ hx)
{
    __shared__ float red[256];
    __shared__ float s_mean, s_rstd;
    int row = blockIdx.x;
    int tid = threadIdx.x;
    const float* orow = o + (size_t)row * DM;
    float*       xrow = x + (size_t)row * DM;
    __half*      hrow = hx + (size_t)row * DM;

    float s = 0.f;
    for (int d = tid; d < DM; d += 256) s += orow[d];
    red[tid] = s; __syncthreads();
    for (int off = 128; off > 0; off >>= 1) {
        if (tid < off) red[tid] += red[tid + off];
        __syncthreads();
    }
    if (tid == 0) s_mean = red[0] * (1.f / DM);
    __syncthreads();
    float mean = s_mean;

    float vv = 0.f;
    for (int d = tid; d < DM; d += 256) { float t = orow[d] - mean; vv += t * t; }
    red[tid] = vv; __syncthreads();
    for (int off = 128; off > 0; off >>= 1) {
        if (tid < off) red[tid] += red[tid + off];
        __syncthreads();
    }
    if (tid == 0) s_rstd = rsqrtf(red[0] * (1.f / DM) + 1e-5f);
    __syncthreads();
    float rstd = s_rstd;

    for (int d = tid; d < DM; d += 256){
        float v = xrow[d] + (orow[d] - mean) * rstd * g[d] + b[d];
        xrow[d] = v;
        hrow[d] = __float2half_rn(v);
    }
}

// ---------------- launch ----------------------------------------------------
extern "C" void kernel_launch(void* const* d_in, const int* in_sizes, int n_in,
                              void* d_out, int out_size)
{
    const int*   tokens = (const int*)  d_in[0];
    const float* emb    = (const float*)d_in[1];
    const float* pe     = (const float*)d_in[2];
    const float* Wq     = (const float*)d_in[3];
    const float* bq     = (const float*)d_in[4];
    const float* Wk     = (const float*)d_in[5];
    const float* bk     = (const float*)d_in[6];
    const float* Wv     = (const float*)d_in[7];
    const float* bv     = (const float*)d_in[8];
    const float* Wo     = (const float*)d_in[9];
    const float* bo     = (const float*)d_in[10];
    const float* g1     = (const float*)d_in[11];
    const float* be1    = (const float*)d_in[12];
    const float* W1     = (const float*)d_in[13];
    const float* b1     = (const float*)d_in[14];
    const float* W2     = (const float*)d_in[15];
    const float* b2     = (const float*)d_in[16];
    const float* g2     = (const float*)d_in[17];
    const float* be2    = (const float*)d_in[18];
    const float* Wfc    = (const float*)d_in[19];
    const float* bfc    = (const float*)d_in[20];
    float* out = (float*)d_out;

    float *x, *t0, *t3, *qkv, *bqkv;
    __half *hWqkv, *hWo, *hW1, *hW2, *hWfc, *hx, *ht3, *hf1;
    cudaGetSymbolAddress((void**)&x,   g_x);
    cudaGetSymbolAddress((void**)&t0,  g_t0);
    cudaGetSymbolAddress((void**)&t3,  g_t3);
    cudaGetSymbolAddress((void**)&qkv, g_qkv);
    cudaGetSymbolAddress((void**)&bqkv, g_bqkv);
    cudaGetSymbolAddress((void**)&hWqkv, g_hWqkv);
    cudaGetSymbolAddress((void**)&hWo, g_hWo);
    cudaGetSymbolAddress((void**)&hW1, g_hW1);
    cudaGetSymbolAddress((void**)&hW2, g_hW2);
    cudaGetSymbolAddress((void**)&hWfc, g_hWfc);
    cudaGetSymbolAddress((void**)&hx,  g_hx);
    cudaGetSymbolAddress((void**)&ht3, g_ht3);
    cudaGetSymbolAddress((void**)&hf1, g_hf1);

    cudaFuncSetAttribute(attn_kernel,
                         cudaFuncAttributeMaxDynamicSharedMemorySize, ATTN_SMEM);
    cudaFuncSetAttribute(hgemm<false,false>,
                         cudaFuncAttributeMaxDynamicSharedMemorySize, GEMM_SMEM);
    cudaFuncSetAttribute(hgemm<true,true>,
                         cudaFuncAttributeMaxDynamicSharedMemorySize, GEMM_SMEM);

    const int CB = 256;
    pack_qkv_w<<<(int)(((long long)NL*DM*DM3/4 + CB-1)/CB), CB>>>(Wq, Wk, Wv, hWqkv);
    pack_qkv_b<<<(NL*DM3 + CB-1)/CB, CB>>>(bq, bk, bv, bqkv);
    cvt_f2h<<<(NL*DM*DM/4 + CB-1)/CB, CB>>>(Wo, hWo, NL*DM*DM);
    cvt_f2h<<<(NL*DM*DFF/4 + CB-1)/CB, CB>>>(W1, hW1, NL*DM*DFF);
    cvt_f2h<<<(NL*DFF*DM/4 + CB-1)/CB, CB>>>(W2, hW2, NL*DFF*DM);
    cvt_f2h<<<(DM*VOCAB/4 + CB-1)/CB, CB>>>(Wfc, hWfc, DM*VOCAB);

    embed_kernel<<<(MROWS * DM + 255) / 256, 256>>>(tokens, emb, pe, x, hx);

    dim3 gQKV(MROWS / 128, DM3 / 128);  // (16, 24)
    dim3 gDD(MROWS / 128, DM / 128);    // (16, 8)
    dim3 gDF(MROWS / 128, DFF / 128);   // (16, 32)
    dim3 gAttn(SEQ / 128, NH, BATCH);

    for (int l = 0; l < NL; l++) {
        const __half* wqkv = hWqkv + (size_t)l * DM * DM3;
        const __half* wo = hWo + (size_t)l * DM * DM;
        const __half* w1 = hW1 + (size_t)l * DM * DFF;
        const __half* w2 = hW2 + (size_t)l * DFF * DM;

        hgemm<false,false><<<gQKV, 256, GEMM_SMEM>>>(hx, wqkv, bqkv + l * DM3, qkv, DM3, DM);

        attn_kernel<<<gAttn, 128, ATTN_SMEM>>>(qkv, t3, ht3);

        hgemm<false,false><<<gDD, 256, GEMM_SMEM>>>(ht3, wo, bo + l * DM, t0, DM, DM);
        ln_residual<<<MROWS, 256>>>(x, t0, g1 + l * DM, be1 + l * DM, hx);

        hgemm<true,true ><<<gDF, 256, GEMM_SMEM>>>(hx, w1, b1 + l * DFF, hf1, DFF, DM);
        hgemm<false,false><<<gDD, 256, GEMM_SMEM>>>(hf1, w2, b2 + l * DM, t0, DM, DFF);
        ln_residual<<<MROWS, 256>>>(x, t0, g2 + l * DM, be2 + l * DM, hx);
    }

    dim3 gV(MROWS / 128, VOCAB / 128);  // (16, 250)
    hgemm<false,false><<<gV, 256, GEMM_SMEM>>>(hx, hWfc, bfc, out, VOCAB, DM);
}

// round 12
// speedup vs baseline: 4.0571x; 1.8413x over previous
#include <cuda_runtime.h>
#include <cuda_bf16.h>
#include <cuda_fp16.h>
#include <math.h>
#include <stdint.h>

#define BATCH 4
#define SEQ   512
#define DM    1024
#define NH    16
#define NL    8
#define VOCAB 32000
#define HDIM  64
#define DFF   4096
#define MROWS (BATCH*SEQ)
#define DM3   (3*DM)

// fp32 scratch
__device__ float g_x  [MROWS*DM];
__device__ float g_t0 [MROWS*DM];
// fp16 weights / activations
__device__ __half g_hWqkv[NL*DM*DM3];
__device__ __half g_hWo[NL*DM*DM];
__device__ __half g_hW1[NL*DM*DFF];
__device__ __half g_hW2[NL*DFF*DM];
__device__ __half g_hWfc[DM*VOCAB];
__device__ __half g_hx  [MROWS*DM];
__device__ __half g_ht3 [MROWS*DM];
__device__ __half g_hf1 [MROWS*DFF];
__device__ __half g_hqkv[MROWS*DM3];
__device__ float  g_bqkv[NL*DM3];

__device__ __forceinline__ uint32_t h2pk(float x, float y){
    __half2 h = __floats2half2_rn(x, y);
    return *(uint32_t*)&h;
}

__global__ void cvt_f2h(const float* __restrict__ s, __half* __restrict__ d, int n){
    int i = (blockIdx.x * blockDim.x + threadIdx.x) * 4;
    if (i >= n) return;
    float4 v = *(const float4*)(s + i);
    uint2 h = make_uint2(h2pk(v.x, v.y), h2pk(v.z, v.w));
    *(uint2*)(d + i) = h;
}

__global__ void pack_qkv_w(const float* __restrict__ Wq, const float* __restrict__ Wk,
                           const float* __restrict__ Wv, __half* __restrict__ d)
{
    long long i = ((long long)blockIdx.x * blockDim.x + threadIdx.x) * 4;
    if (i >= (long long)NL * DM * DM3) return;
    int l = (int)(i / ((long long)DM * DM3));
    long long rem = i % ((long long)DM * DM3);
    int k = (int)(rem / DM3);
    int c = (int)(rem % DM3);
    const float* src = (c < DM) ? Wq : ((c < 2*DM) ? Wk : Wv);
    int sc = c % DM;
    float4 v = *(const float4*)(src + (size_t)l * DM * DM + (size_t)k * DM + sc);
    uint2 h = make_uint2(h2pk(v.x, v.y), h2pk(v.z, v.w));
    *(uint2*)(d + i) = h;
}
__global__ void pack_qkv_b(const float* __restrict__ bq, const float* __restrict__ bk,
                           const float* __restrict__ bv, float* __restrict__ d)
{
    int i = blockIdx.x * blockDim.x + threadIdx.x;
    if (i >= NL * DM3) return;
    int l = i / DM3, c = i % DM3;
    const float* src = (c < DM) ? bq : ((c < 2*DM) ? bk : bv);
    d[i] = src[(size_t)l * DM + (c % DM)];
}

__global__ void embed_kernel(const int* __restrict__ tokens,
                             const float* __restrict__ emb,
                             const float* __restrict__ pe,
                             float* __restrict__ x, __half* __restrict__ hx)
{
    int idx = blockIdx.x * blockDim.x + threadIdx.x;
    if (idx >= MROWS * DM) return;
    int d  = idx % DM;
    int nt = idx / DM;
    int n  = nt / SEQ;
    int tok = tokens[nt];
    float v = emb[(size_t)tok * DM + d] + pe[(size_t)n * DM + d];
    x[idx] = v;
    hx[idx] = __float2half_rn(v);
}

// ---------------- shared PTX helpers ----------------------------------------
__device__ __forceinline__ uint32_t cvta_smem(const void* p){
    uint32_t a;
    asm("{ .reg .u64 t; cvta.to.shared.u64 t, %1; cvt.u32.u64 %0, t; }" : "=r"(a) : "l"(p));
    return a;
}
__device__ __forceinline__ void cpa16(uint32_t daddr, const void* g){
    asm volatile("cp.async.cg.shared.global [%0], [%1], 16;" :: "r"(daddr), "l"(g));
}
__device__ __forceinline__ void cp_commit(){ asm volatile("cp.async.commit_group;"); }
__device__ __forceinline__ void cp_wait1(){ asm volatile("cp.async.wait_group 1;"); }
__device__ __forceinline__ void cp_wait0(){ asm volatile("cp.async.wait_group 0;"); }
__device__ __forceinline__ void ldm4(uint32_t* r, uint32_t addr){
    asm volatile("ldmatrix.sync.aligned.m8n8.x4.shared.b16 {%0,%1,%2,%3}, [%4];"
                 : "=r"(r[0]), "=r"(r[1]), "=r"(r[2]), "=r"(r[3]) : "r"(addr));
}
__device__ __forceinline__ void ldm4t(uint32_t* r, uint32_t addr){
    asm volatile("ldmatrix.sync.aligned.m8n8.x4.trans.shared.b16 {%0,%1,%2,%3}, [%4];"
                 : "=r"(r[0]), "=r"(r[1]), "=r"(r[2]), "=r"(r[3]) : "r"(addr));
}
__device__ __forceinline__ void mma_f16(float* c, const uint32_t* a, const uint32_t* b){
    asm volatile(
        "mma.sync.aligned.m16n8k16.row.col.f32.f16.f16.f32 "
        "{%0,%1,%2,%3}, {%4,%5,%6,%7}, {%8,%9}, {%0,%1,%2,%3};"
        : "+f"(c[0]), "+f"(c[1]), "+f"(c[2]), "+f"(c[3])
        : "r"(a[0]), "r"(a[1]), "r"(a[2]), "r"(a[3]), "r"(b[0]), "r"(b[1]));
}

// ===== fp16 cp.async GEMM ====================================================
#define PADA_H 72
#define PADB_H 136
#define A_BYTES (128*PADA_H*2)
#define B_BYTES (64*PADB_H*2)
#define STG_BYTES (A_BYTES + B_BYTES)
#define GEMM_SMEM (3*STG_BYTES)

template<bool RELU, bool OUTH>
__global__ void __launch_bounds__(256, 2)
hgemm(const __half* __restrict__ A, const __half* __restrict__ B,
      const float* __restrict__ bias, void* __restrict__ Cout,
      int Nn, int K)
{
    extern __shared__ __half smem[];
    const int tid = threadIdx.x, lane = tid & 31, warp = tid >> 5;
    const int warp_m = warp & 1, warp_n = warp >> 1;
    const int mbase = blockIdx.x * 128, nbase = blockIdx.y * 128;

    const __half* Ag = A + (size_t)mbase * K;
    const __half* Bg = B + nbase;
    const int NC = K >> 6;

    const uint32_t smem_u = cvta_smem(smem);
    const int a_row = tid >> 3, a_c8 = tid & 7;
    const int b_row = tid >> 4, b_c16 = tid & 15;

    const int g = lane >> 2, tig = lane & 3;
    const int sel = lane >> 3, l7 = lane & 7;
    uint32_t a_rel[4], b_rel[2];
#pragma unroll
    for (int mt = 0; mt < 4; mt++){
        int row = warp_m * 64 + mt * 16 + (sel & 1) * 8 + l7;
        a_rel[mt] = (uint32_t)(row * (PADA_H*2)) + (uint32_t)((sel >> 1) * 16);
    }
#pragma unroll
    for (int np2 = 0; np2 < 2; np2++){
        int krow = (sel & 1) * 8 + l7;
        int ncol = warp_n * 32 + np2 * 16 + (sel >> 1) * 8;
        b_rel[np2] = (uint32_t)A_BYTES + (uint32_t)(krow * (PADB_H*2)) + (uint32_t)(ncol * 2);
    }

    float acc[4][4][4];
#pragma unroll
    for (int mt = 0; mt < 4; mt++)
#pragma unroll
        for (int np = 0; np < 4; np++)
#pragma unroll
            for (int i = 0; i < 4; i++) acc[mt][np][i] = 0.f;

    auto issue_stage = [&](int chunk, int buf){
        uint32_t base = smem_u + (uint32_t)buf * STG_BYTES;
        const __half* As = Ag + (size_t)chunk * 64;
#pragma unroll
        for (int p = 0; p < 4; p++){
            int row = a_row + p * 32;
            cpa16(base + row * (PADA_H*2) + a_c8 * 16,
                  As + (size_t)row * K + a_c8 * 8);
        }
        const __half* Bs = Bg + (size_t)(chunk * 64) * Nn;
#pragma unroll
        for (int p = 0; p < 4; p++){
            int row = b_row + p * 16;
            cpa16(base + A_BYTES + row * (PADB_H*2) + b_c16 * 16,
                  Bs + (size_t)row * Nn + b_c16 * 8);
        }
        cp_commit();
    };

    issue_stage(0, 0);
    if (NC > 1) issue_stage(1, 1);

    int buf = 0;
    for (int c = 0; c < NC; c++){
        if (c + 1 < NC) cp_wait1(); else cp_wait0();
        __syncthreads();
        if (c + 2 < NC){
            int nb = buf + 2; if (nb >= 3) nb -= 3;
            issue_stage(c + 2, nb);
        }

        const uint32_t sbase = smem_u + (uint32_t)buf * STG_BYTES;
#pragma unroll
        for (int ks = 0; ks < 4; ks++){
            uint32_t af[16], bf[8];
#pragma unroll
            for (int mt = 0; mt < 4; mt++)
                ldm4(&af[4*mt], sbase + a_rel[mt] + ks * 32);
#pragma unroll
            for (int np2 = 0; np2 < 2; np2++)
                ldm4t(&bf[4*np2], sbase + b_rel[np2] + ks * 16 * (PADB_H*2));
#pragma unroll
            for (int mt = 0; mt < 4; mt++)
#pragma unroll
                for (int np = 0; np < 4; np++)
                    mma_f16(acc[mt][np], &af[4*mt], &bf[2*np]);
        }

        if (++buf == 3) buf = 0;
    }

#pragma unroll
    for (int mt = 0; mt < 4; mt++){
        int row0 = mbase + warp_m * 64 + mt * 16 + g;
#pragma unroll
        for (int np = 0; np < 4; np++){
            int col = nbase + warp_n * 32 + np * 8 + 2 * tig;
            float b0 = bias[col], b1 = bias[col + 1];
            float2 v0 = make_float2(acc[mt][np][0] + b0, acc[mt][np][1] + b1);
            float2 v1 = make_float2(acc[mt][np][2] + b0, acc[mt][np][3] + b1);
            if (RELU){
                v0.x = fmaxf(v0.x, 0.f); v0.y = fmaxf(v0.y, 0.f);
                v1.x = fmaxf(v1.x, 0.f); v1.y = fmaxf(v1.y, 0.f);
            }
            if (OUTH){
                __half* Ch = (__half*)Cout;
                *(uint32_t*)&Ch[(size_t)row0 * Nn + col]       = h2pk(v0.x, v0.y);
                *(uint32_t*)&Ch[(size_t)(row0 + 8) * Nn + col] = h2pk(v1.x, v1.y);
            } else {
                float* C = (float*)Cout;
                *(float2*)&C[(size_t)row0 * Nn + col]       = v0;
                *(float2*)&C[(size_t)(row0 + 8) * Nn + col] = v1;
            }
        }
    }
}

// ===== tensor-core causal flash attention (fp16 in, fp32 softmax/accum) ======
// grid (SEQ/64, NH, BATCH), 128 threads (4 warps x 16 q-rows).
#define PADH 72

__global__ void __launch_bounds__(128)
fattn(const __half* __restrict__ qkv, __half* __restrict__ o)
{
    __shared__ __half sQ[64*PADH];
    __shared__ __half sK[2][64*PADH];
    __shared__ __half sV[2][64*PADH];

    const int n = blockIdx.z, h = blockIdx.y, qb = blockIdx.x;
    const int tid = threadIdx.x, lane = tid & 31, warp = tid >> 5;
    const int g = lane >> 2, tig = lane & 3;
    const int sel = lane >> 3, l7 = lane & 7;

    const __half* Qg = qkv + ((size_t)(n*SEQ + qb*64))*DM3 + h*HDIM;
    const __half* Kg = qkv + ((size_t)(n*SEQ))*DM3 + DM + h*HDIM;
    const __half* Vg = qkv + ((size_t)(n*SEQ))*DM3 + 2*DM + h*HDIM;

    // load Q tile 64x64 (sync)
    {
        int row = tid >> 1, c0 = (tid & 1) * 4;
        const uint4* src = (const uint4*)(Qg + (size_t)row * DM3);
        uint4* dst = (uint4*)(sQ + row * PADH);
#pragma unroll
        for (int i = 0; i < 4; i++) dst[c0 + i] = src[c0 + i];
    }
    __syncthreads();

    // Q fragments (m16 x k64 per warp)
    uint32_t qf[4][4];
    {
        uint32_t base = cvta_smem(sQ);
#pragma unroll
        for (int kc = 0; kc < 4; kc++){
            uint32_t addr = base + (uint32_t)((warp*16 + (sel&1)*8 + l7) * (PADH*2))
                          + (uint32_t)((sel>>1)*16 + kc*32);
            ldm4(qf[kc], addr);
        }
    }

    auto issue_kv = [&](int t, int buf){
        int row = tid >> 1, c0 = (tid & 1) * 4;
        const __half* kg = Kg + (size_t)(t*64 + row) * DM3;
        const __half* vg = Vg + (size_t)(t*64 + row) * DM3;
        uint32_t kb = cvta_smem(sK[buf]) + row * (PADH*2);
        uint32_t vb = cvta_smem(sV[buf]) + row * (PADH*2);
#pragma unroll
        for (int i = 0; i < 4; i++){
            cpa16(kb + (c0+i)*16, kg + (c0+i)*8);
            cpa16(vb + (c0+i)*16, vg + (c0+i)*8);
        }
        cp_commit();
    };

    float m0 = -1e30f, m1 = -1e30f, l0 = 0.f, l1 = 0.f;
    float oacc[8][4];
#pragma unroll
    for (int nb = 0; nb < 8; nb++)
#pragma unroll
        for (int i = 0; i < 4; i++) oacc[nb][i] = 0.f;

    const int nt = qb + 1;
    issue_kv(0, 0);

    for (int t = 0; t < nt; t++){
        if (t + 1 < nt){ issue_kv(t + 1, (t + 1) & 1); cp_wait1(); }
        else cp_wait0();
        __syncthreads();
        const int buf = t & 1;

        // S = Q @ K^T (scores, fp32)
        float sc[8][4];
#pragma unroll
        for (int nb = 0; nb < 8; nb++)
#pragma unroll
            for (int i = 0; i < 4; i++) sc[nb][i] = 0.f;

        uint32_t kbase = cvta_smem(sK[buf]);
#pragma unroll
        for (int kc = 0; kc < 4; kc++){
            uint32_t kf[16];
#pragma unroll
            for (int nb16 = 0; nb16 < 4; nb16++){
                uint32_t addr = kbase + (uint32_t)((nb16*16 + (sel>>1)*8 + l7) * (PADH*2))
                              + (uint32_t)((sel&1)*16 + kc*32);
                ldm4(&kf[nb16*4], addr);
            }
#pragma unroll
            for (int nb16 = 0; nb16 < 4; nb16++){
                mma_f16(sc[2*nb16],   qf[kc], &kf[nb16*4]);
                mma_f16(sc[2*nb16+1], qf[kc], &kf[nb16*4 + 2]);
            }
        }

        // scale + causal mask (diagonal tile only)
#pragma unroll
        for (int nb = 0; nb < 8; nb++)
#pragma unroll
            for (int i = 0; i < 4; i++) sc[nb][i] *= 0.125f;
        if (t == qb){
            int row0 = warp*16 + g, row1 = row0 + 8;
#pragma unroll
            for (int nb = 0; nb < 8; nb++){
                int cb = nb*8 + 2*tig;
                if (cb     > row0) sc[nb][0] = -1e30f;
                if (cb + 1 > row0) sc[nb][1] = -1e30f;
                if (cb     > row1) sc[nb][2] = -1e30f;
                if (cb + 1 > row1) sc[nb][3] = -1e30f;
            }
        }

        // online softmax
        float tm0 = -1e30f, tm1 = -1e30f;
#pragma unroll
        for (int nb = 0; nb < 8; nb++){
            tm0 = fmaxf(tm0, fmaxf(sc[nb][0], sc[nb][1]));
            tm1 = fmaxf(tm1, fmaxf(sc[nb][2], sc[nb][3]));
        }
        tm0 = fmaxf(tm0, __shfl_xor_sync(0xffffffffu, tm0, 1));
        tm0 = fmaxf(tm0, __shfl_xor_sync(0xffffffffu, tm0, 2));
        tm1 = fmaxf(tm1, __shfl_xor_sync(0xffffffffu, tm1, 1));
        tm1 = fmaxf(tm1, __shfl_xor_sync(0xffffffffu, tm1, 2));

        float nm0 = fmaxf(m0, tm0), nm1 = fmaxf(m1, tm1);
        float cf0 = __expf(m0 - nm0), cf1 = __expf(m1 - nm1);
        l0 *= cf0; l1 *= cf1;
#pragma unroll
        for (int nb = 0; nb < 8; nb++){
            oacc[nb][0] *= cf0; oacc[nb][1] *= cf0;
            oacc[nb][2] *= cf1; oacc[nb][3] *= cf1;
        }
        float rs0 = 0.f, rs1 = 0.f;
#pragma unroll
        for (int nb = 0; nb < 8; nb++){
            sc[nb][0] = __expf(sc[nb][0] - nm0);
            sc[nb][1] = __expf(sc[nb][1] - nm0);
            sc[nb][2] = __expf(sc[nb][2] - nm1);
            sc[nb][3] = __expf(sc[nb][3] - nm1);
            rs0 += sc[nb][0] + sc[nb][1];
            rs1 += sc[nb][2] + sc[nb][3];
        }
        rs0 += __shfl_xor_sync(0xffffffffu, rs0, 1);
        rs0 += __shfl_xor_sync(0xffffffffu, rs0, 2);
        rs1 += __shfl_xor_sync(0xffffffffu, rs1, 1);
        rs1 += __shfl_xor_sync(0xffffffffu, rs1, 2);
        l0 += rs0; l1 += rs1; m0 = nm0; m1 = nm1;

        // O += P @ V
        uint32_t vbase = cvta_smem(sV[buf]);
#pragma unroll
        for (int kc = 0; kc < 4; kc++){
            uint32_t pa[4];
            pa[0] = h2pk(sc[2*kc][0],   sc[2*kc][1]);
            pa[1] = h2pk(sc[2*kc][2],   sc[2*kc][3]);
            pa[2] = h2pk(sc[2*kc+1][0], sc[2*kc+1][1]);
            pa[3] = h2pk(sc[2*kc+1][2], sc[2*kc+1][3]);
            uint32_t vf[16];
#pragma unroll
            for (int db = 0; db < 4; db++){
                uint32_t addr = vbase + (uint32_t)((kc*16 + (sel&1)*8 + l7) * (PADH*2))
                              + (uint32_t)(db*32 + (sel>>1)*16);
                ldm4t(&vf[db*4], addr);
            }
#pragma unroll
            for (int db = 0; db < 4; db++){
                mma_f16(oacc[2*db],   pa, &vf[db*4]);
                mma_f16(oacc[2*db+1], pa, &vf[db*4 + 2]);
            }
        }
        __syncthreads();
    }

    // write O (fp16), normalized
    float inv0 = 1.f / l0, inv1 = 1.f / l1;
    int row0 = n*SEQ + qb*64 + warp*16 + g;
#pragma unroll
    for (int nb = 0; nb < 8; nb++){
        int col = h*HDIM + nb*8 + 2*tig;
        *(uint32_t*)&o[(size_t)row0 * DM + col] =
            h2pk(oacc[nb][0]*inv0, oacc[nb][1]*inv0);
        *(uint32_t*)&o[(size_t)(row0 + 8) * DM + col] =
            h2pk(oacc[nb][2]*inv1, oacc[nb][3]*inv1);
    }
}

// ---- residual + LayerNorm: x += LN(o)*g + b ; also emit fp16 x --------------
__global__ void __launch_bounds__(256)
ln_residual(float* __restrict__ x, const float* __restrict__ o,
            const float* __restrict__ g, const float* __restrict__ b,
            __half* __restrict__ hx)
{
    __shared__ float red[256];
    __shared__ float s_mean, s_rstd;
    int row = blockIdx.x;
    int tid = threadIdx.x;
    const float* orow = o + (size_t)row * DM;
    float*       xrow = x + (size_t)row * DM;
    __half*      hrow = hx + (size_t)row * DM;

    float s = 0.f;
    for (int d = tid; d < DM; d += 256) s += orow[d];
    red[tid] = s; __syncthreads();
    for (int off = 128; off > 0; off >>= 1) {
        if (tid < off) red[tid] += red[tid + off];
        __syncthreads();
    }
    if (tid == 0) s_mean = red[0] * (1.f / DM);
    __syncthreads();
    float mean = s_mean;

    float vv = 0.f;
    for (int d = tid; d < DM; d += 256) { float t = orow[d] - mean; vv += t * t; }
    red[tid] = vv; __syncthreads();
    for (int off = 128; off > 0; off >>= 1) {
        if (tid < off) red[tid] += red[tid + off];
        __syncthreads();
    }
    if (tid == 0) s_rstd = rsqrtf(red[0] * (1.f / DM) + 1e-5f);
    __syncthreads();
    float rstd = s_rstd;

    for (int d = tid; d < DM; d += 256){
        float v = xrow[d] + (orow[d] - mean) * rstd * g[d] + b[d];
        xrow[d] = v;
        hrow[d] = __float2half_rn(v);
    }
}

// ---------------- launch ----------------------------------------------------
extern "C" void kernel_launch(void* const* d_in, const int* in_sizes, int n_in,
                              void* d_out, int out_size)
{
    const int*   tokens = (const int*)  d_in[0];
    const float* emb    = (const float*)d_in[1];
    const float* pe     = (const float*)d_in[2];
    const float* Wq     = (const float*)d_in[3];
    const float* bq     = (const float*)d_in[4];
    const float* Wk     = (const float*)d_in[5];
    const float* bk     = (const float*)d_in[6];
    const float* Wv     = (const float*)d_in[7];
    const float* bv     = (const float*)d_in[8];
    const float* Wo     = (const float*)d_in[9];
    const float* bo     = (const float*)d_in[10];
    const float* g1     = (const float*)d_in[11];
    const float* be1    = (const float*)d_in[12];
    const float* W1     = (const float*)d_in[13];
    const float* b1     = (const float*)d_in[14];
    const float* W2     = (const float*)d_in[15];
    const float* b2     = (const float*)d_in[16];
    const float* g2     = (const float*)d_in[17];
    const float* be2    = (const float*)d_in[18];
    const float* Wfc    = (const float*)d_in[19];
    const float* bfc    = (const float*)d_in[20];
    float* out = (float*)d_out;

    float *x, *t0, *bqkv;
    __half *hWqkv, *hWo, *hW1, *hW2, *hWfc, *hx, *ht3, *hf1, *hqkv;
    cudaGetSymbolAddress((void**)&x,   g_x);
    cudaGetSymbolAddress((void**)&t0,  g_t0);
    cudaGetSymbolAddress((void**)&bqkv, g_bqkv);
    cudaGetSymbolAddress((void**)&hWqkv, g_hWqkv);
    cudaGetSymbolAddress((void**)&hWo, g_hWo);
    cudaGetSymbolAddress((void**)&hW1, g_hW1);
    cudaGetSymbolAddress((void**)&hW2, g_hW2);
    cudaGetSymbolAddress((void**)&hWfc, g_hWfc);
    cudaGetSymbolAddress((void**)&hx,  g_hx);
    cudaGetSymbolAddress((void**)&ht3, g_ht3);
    cudaGetSymbolAddress((void**)&hf1, g_hf1);
    cudaGetSymbolAddress((void**)&hqkv, g_hqkv);

    cudaFuncSetAttribute(hgemm<false,false>,
                         cudaFuncAttributeMaxDynamicSharedMemorySize, GEMM_SMEM);
    cudaFuncSetAttribute(hgemm<false,true>,
                         cudaFuncAttributeMaxDynamicSharedMemorySize, GEMM_SMEM);
    cudaFuncSetAttribute(hgemm<true,true>,
                         cudaFuncAttributeMaxDynamicSharedMemorySize, GEMM_SMEM);

    const int CB = 256;
    pack_qkv_w<<<(int)(((long long)NL*DM*DM3/4 + CB-1)/CB), CB>>>(Wq, Wk, Wv, hWqkv);
    pack_qkv_b<<<(NL*DM3 + CB-1)/CB, CB>>>(bq, bk, bv, bqkv);
    cvt_f2h<<<(NL*DM*DM/4 + CB-1)/CB, CB>>>(Wo, hWo, NL*DM*DM);
    cvt_f2h<<<(NL*DM*DFF/4 + CB-1)/CB, CB>>>(W1, hW1, NL*DM*DFF);
    cvt_f2h<<<(NL*DFF*DM/4 + CB-1)/CB, CB>>>(W2, hW2, NL*DFF*DM);
    cvt_f2h<<<(DM*VOCAB/4 + CB-1)/CB, CB>>>(Wfc, hWfc, DM*VOCAB);

    embed_kernel<<<(MROWS * DM + 255) / 256, 256>>>(tokens, emb, pe, x, hx);

    dim3 gQKV(MROWS / 128, DM3 / 128);  // (16, 24)
    dim3 gDD(MROWS / 128, DM / 128);    // (16, 8)
    dim3 gDF(MROWS / 128, DFF / 128);   // (16, 32)
    dim3 gAttn(SEQ / 64, NH, BATCH);    // (8, 16, 4)

    for (int l = 0; l < NL; l++) {
        const __half* wqkv = hWqkv + (size_t)l * DM * DM3;
        const __half* wo = hWo + (size_t)l * DM * DM;
        const __half* w1 = hW1 + (size_t)l * DM * DFF;
        const __half* w2 = hW2 + (size_t)l * DFF * DM;

        hgemm<false,true><<<gQKV, 256, GEMM_SMEM>>>(hx, wqkv, bqkv + l * DM3, hqkv, DM3, DM);

        fattn<<<gAttn, 128>>>(hqkv, ht3);

        hgemm<false,false><<<gDD, 256, GEMM_SMEM>>>(ht3, wo, bo + l * DM, t0, DM, DM);
        ln_residual<<<MROWS, 256>>>(x, t0, g1 + l * DM, be1 + l * DM, hx);

        hgemm<true,true ><<<gDF, 256, GEMM_SMEM>>>(hx, w1, b1 + l * DFF, hf1, DFF, DM);
        hgemm<false,false><<<gDD, 256, GEMM_SMEM>>>(hf1, w2, b2 + l * DM, t0, DM, DFF);
        ln_residual<<<MROWS, 256>>>(x, t0, g2 + l * DM, be2 + l * DM, hx);
    }

    dim3 gV(MROWS / 128, VOCAB / 128);  // (16, 250)
    hgemm<false,false><<<gV, 256, GEMM_SMEM>>>(hx, hWfc, bfc, out, VOCAB, DM);
}

// round 14
// speedup vs baseline: 4.1378x; 1.0199x over previous
#include <cuda_runtime.h>
#include <cuda_bf16.h>
#include <cuda_fp16.h>
#include <math.h>
#include <stdint.h>

#define BATCH 4
#define SEQ   512
#define DM    1024
#define NH    16
#define NL    8
#define VOCAB 32000
#define HDIM  64
#define DFF   4096
#define MROWS (BATCH*SEQ)
#define DM3   (3*DM)

// fp32 scratch
__device__ float g_x  [MROWS*DM];
__device__ float g_t0 [MROWS*DM];
// fp16 weights / activations
__device__ __half g_hWqkv[NL*DM*DM3];
__device__ __half g_hWo[NL*DM*DM];
__device__ __half g_hW1[NL*DM*DFF];
__device__ __half g_hW2[NL*DFF*DM];
__device__ __half g_hWfc[DM*VOCAB];
__device__ __half g_hx  [MROWS*DM];
__device__ __half g_ht3 [MROWS*DM];
__device__ __half g_hf1 [MROWS*DFF];
__device__ __half g_hqkv[MROWS*DM3];
__device__ float  g_bqkv[NL*DM3];

__device__ __forceinline__ uint32_t h2pk(float x, float y){
    __half2 h = __floats2half2_rn(x, y);
    return *(uint32_t*)&h;
}

__global__ void cvt_f2h(const float* __restrict__ s, __half* __restrict__ d, int n){
    int i = (blockIdx.x * blockDim.x + threadIdx.x) * 4;
    if (i >= n) return;
    float4 v = *(const float4*)(s + i);
    uint2 h = make_uint2(h2pk(v.x, v.y), h2pk(v.z, v.w));
    *(uint2*)(d + i) = h;
}

__global__ void pack_qkv_w(const float* __restrict__ Wq, const float* __restrict__ Wk,
                           const float* __restrict__ Wv, __half* __restrict__ d)
{
    long long i = ((long long)blockIdx.x * blockDim.x + threadIdx.x) * 4;
    if (i >= (long long)NL * DM * DM3) return;
    int l = (int)(i / ((long long)DM * DM3));
    long long rem = i % ((long long)DM * DM3);
    int k = (int)(rem / DM3);
    int c = (int)(rem % DM3);
    const float* src = (c < DM) ? Wq : ((c < 2*DM) ? Wk : Wv);
    int sc = c % DM;
    float4 v = *(const float4*)(src + (size_t)l * DM * DM + (size_t)k * DM + sc);
    uint2 h = make_uint2(h2pk(v.x, v.y), h2pk(v.z, v.w));
    *(uint2*)(d + i) = h;
}
__global__ void pack_qkv_b(const float* __restrict__ bq, const float* __restrict__ bk,
                           const float* __restrict__ bv, float* __restrict__ d)
{
    int i = blockIdx.x * blockDim.x + threadIdx.x;
    if (i >= NL * DM3) return;
    int l = i / DM3, c = i % DM3;
    const float* src = (c < DM) ? bq : ((c < 2*DM) ? bk : bv);
    d[i] = src[(size_t)l * DM + (c % DM)];
}

__global__ void embed_kernel(const int* __restrict__ tokens,
                             const float* __restrict__ emb,
                             const float* __restrict__ pe,
                             float* __restrict__ x, __half* __restrict__ hx)
{
    int idx = blockIdx.x * blockDim.x + threadIdx.x;
    if (idx >= MROWS * DM) return;
    int d  = idx % DM;
    int nt = idx / DM;
    int n  = nt / SEQ;
    int tok = tokens[nt];
    float v = emb[(size_t)tok * DM + d] + pe[(size_t)n * DM + d];
    x[idx] = v;
    hx[idx] = __float2half_rn(v);
}

// ---------------- shared PTX helpers ----------------------------------------
__device__ __forceinline__ uint32_t cvta_smem(const void* p){
    uint32_t a;
    asm("{ .reg .u64 t; cvta.to.shared.u64 t, %1; cvt.u32.u64 %0, t; }" : "=r"(a) : "l"(p));
    return a;
}
__device__ __forceinline__ void cpa16(uint32_t daddr, const void* g){
    asm volatile("cp.async.cg.shared.global [%0], [%1], 16;" :: "r"(daddr), "l"(g));
}
__device__ __forceinline__ void cp_commit(){ asm volatile("cp.async.commit_group;"); }
__device__ __forceinline__ void cp_wait1(){ asm volatile("cp.async.wait_group 1;"); }
__device__ __forceinline__ void cp_wait0(){ asm volatile("cp.async.wait_group 0;"); }
__device__ __forceinline__ void ldm4(uint32_t* r, uint32_t addr){
    asm volatile("ldmatrix.sync.aligned.m8n8.x4.shared.b16 {%0,%1,%2,%3}, [%4];"
                 : "=r"(r[0]), "=r"(r[1]), "=r"(r[2]), "=r"(r[3]) : "r"(addr));
}
__device__ __forceinline__ void ldm4t(uint32_t* r, uint32_t addr){
    asm volatile("ldmatrix.sync.aligned.m8n8.x4.trans.shared.b16 {%0,%1,%2,%3}, [%4];"
                 : "=r"(r[0]), "=r"(r[1]), "=r"(r[2]), "=r"(r[3]) : "r"(addr));
}
__device__ __forceinline__ void mma_f16(float* c, const uint32_t* a, const uint32_t* b){
    asm volatile(
        "mma.sync.aligned.m16n8k16.row.col.f32.f16.f16.f32 "
        "{%0,%1,%2,%3}, {%4,%5,%6,%7}, {%8,%9}, {%0,%1,%2,%3};"
        : "+f"(c[0]), "+f"(c[1]), "+f"(c[2]), "+f"(c[3])
        : "r"(a[0]), "r"(a[1]), "r"(a[2]), "r"(a[3]), "r"(b[0]), "r"(b[1]));
}

// ===== fp16 cp.async GEMM (tile AMT*32 x 128, BK=64, 3-stage) ================
// AMT=4 -> 128xN tile (warp tile 64x32); AMT=2 -> 64xN tile (warp tile 32x32).
#define PADA_H 72
#define PADB_H 136
#define B_BYTES (64*PADB_H*2)

template<bool RELU, bool OUTH, int AMT>
__global__ void __launch_bounds__(256, 2)
hgemm(const __half* __restrict__ A, const __half* __restrict__ B,
      const float* __restrict__ bias, void* __restrict__ Cout,
      int Nn, int K)
{
    constexpr int BM = AMT * 32;
    constexpr int A_BY = BM * PADA_H * 2;
    constexpr int STG = A_BY + B_BYTES;

    extern __shared__ __half smem[];
    const int tid = threadIdx.x, lane = tid & 31, warp = tid >> 5;
    const int warp_m = warp & 1, warp_n = warp >> 1;
    const int mbase = blockIdx.x * BM, nbase = blockIdx.y * 128;

    const __half* Ag = A + (size_t)mbase * K;
    const __half* Bg = B + nbase;
    const int NC = K >> 6;

    const uint32_t smem_u = cvta_smem(smem);
    const int a_row = tid >> 3, a_c8 = tid & 7;
    const int b_row = tid >> 4, b_c16 = tid & 15;

    const int g = lane >> 2, tig = lane & 3;
    const int sel = lane >> 3, l7 = lane & 7;
    uint32_t a_rel[AMT], b_rel[2];
#pragma unroll
    for (int mt = 0; mt < AMT; mt++){
        int row = warp_m * (AMT*16) + mt * 16 + (sel & 1) * 8 + l7;
        a_rel[mt] = (uint32_t)(row * (PADA_H*2)) + (uint32_t)((sel >> 1) * 16);
    }
#pragma unroll
    for (int np2 = 0; np2 < 2; np2++){
        int krow = (sel & 1) * 8 + l7;
        int ncol = warp_n * 32 + np2 * 16 + (sel >> 1) * 8;
        b_rel[np2] = (uint32_t)A_BY + (uint32_t)(krow * (PADB_H*2)) + (uint32_t)(ncol * 2);
    }

    float acc[AMT][4][4];
#pragma unroll
    for (int mt = 0; mt < AMT; mt++)
#pragma unroll
        for (int np = 0; np < 4; np++)
#pragma unroll
            for (int i = 0; i < 4; i++) acc[mt][np][i] = 0.f;

    auto issue_stage = [&](int chunk, int buf){
        uint32_t base = smem_u + (uint32_t)buf * STG;
        const __half* As = Ag + (size_t)chunk * 64;
#pragma unroll
        for (int p = 0; p < AMT; p++){
            int row = a_row + p * 32;
            cpa16(base + row * (PADA_H*2) + a_c8 * 16,
                  As + (size_t)row * K + a_c8 * 8);
        }
        const __half* Bs = Bg + (size_t)(chunk * 64) * Nn;
#pragma unroll
        for (int p = 0; p < 4; p++){
            int row = b_row + p * 16;
            cpa16(base + A_BY + row * (PADB_H*2) + b_c16 * 16,
                  Bs + (size_t)row * Nn + b_c16 * 8);
        }
        cp_commit();
    };

    issue_stage(0, 0);
    if (NC > 1) issue_stage(1, 1);

    int buf = 0;
    for (int c = 0; c < NC; c++){
        if (c + 1 < NC) cp_wait1(); else cp_wait0();
        __syncthreads();
        if (c + 2 < NC){
            int nb = buf + 2; if (nb >= 3) nb -= 3;
            issue_stage(c + 2, nb);
        }

        const uint32_t sbase = smem_u + (uint32_t)buf * STG;
#pragma unroll
        for (int ks = 0; ks < 4; ks++){
            uint32_t af[4*AMT], bf[8];
#pragma unroll
            for (int mt = 0; mt < AMT; mt++)
                ldm4(&af[4*mt], sbase + a_rel[mt] + ks * 32);
#pragma unroll
            for (int np2 = 0; np2 < 2; np2++)
                ldm4t(&bf[4*np2], sbase + b_rel[np2] + ks * 16 * (PADB_H*2));
#pragma unroll
            for (int mt = 0; mt < AMT; mt++)
#pragma unroll
                for (int np = 0; np < 4; np++)
                    mma_f16(acc[mt][np], &af[4*mt], &bf[2*np]);
        }

        if (++buf == 3) buf = 0;
    }

#pragma unroll
    for (int mt = 0; mt < AMT; mt++){
        int row0 = mbase + warp_m * (AMT*16) + mt * 16 + g;
#pragma unroll
        for (int np = 0; np < 4; np++){
            int col = nbase + warp_n * 32 + np * 8 + 2 * tig;
            float b0 = bias[col], b1 = bias[col + 1];
            float2 v0 = make_float2(acc[mt][np][0] + b0, acc[mt][np][1] + b1);
            float2 v1 = make_float2(acc[mt][np][2] + b0, acc[mt][np][3] + b1);
            if (RELU){
                v0.x = fmaxf(v0.x, 0.f); v0.y = fmaxf(v0.y, 0.f);
                v1.x = fmaxf(v1.x, 0.f); v1.y = fmaxf(v1.y, 0.f);
            }
            if (OUTH){
                __half* Ch = (__half*)Cout;
                *(uint32_t*)&Ch[(size_t)row0 * Nn + col]       = h2pk(v0.x, v0.y);
                *(uint32_t*)&Ch[(size_t)(row0 + 8) * Nn + col] = h2pk(v1.x, v1.y);
            } else {
                float* C = (float*)Cout;
                *(float2*)&C[(size_t)row0 * Nn + col]       = v0;
                *(float2*)&C[(size_t)(row0 + 8) * Nn + col] = v1;
            }
        }
    }
}

#define GEMM_SMEM_4 (3*(128*PADA_H*2 + B_BYTES))   // 107520
#define GEMM_SMEM_2 (3*( 64*PADA_H*2 + B_BYTES))   // 79872

// ===== tensor-core causal flash attention (fp16 in, fp32 softmax/accum) ======
#define PADH 72

__global__ void __launch_bounds__(128)
fattn(const __half* __restrict__ qkv, __half* __restrict__ o)
{
    __shared__ __half sQ[64*PADH];
    __shared__ __half sK[2][64*PADH];
    __shared__ __half sV[2][64*PADH];

    const int n = blockIdx.z, h = blockIdx.y, qb = blockIdx.x;
    const int tid = threadIdx.x, lane = tid & 31, warp = tid >> 5;
    const int g = lane >> 2, tig = lane & 3;
    const int sel = lane >> 3, l7 = lane & 7;

    const __half* Qg = qkv + ((size_t)(n*SEQ + qb*64))*DM3 + h*HDIM;
    const __half* Kg = qkv + ((size_t)(n*SEQ))*DM3 + DM + h*HDIM;
    const __half* Vg = qkv + ((size_t)(n*SEQ))*DM3 + 2*DM + h*HDIM;

    {
        int row = tid >> 1, c0 = (tid & 1) * 4;
        const uint4* src = (const uint4*)(Qg + (size_t)row * DM3);
        uint4* dst = (uint4*)(sQ + row * PADH);
#pragma unroll
        for (int i = 0; i < 4; i++) dst[c0 + i] = src[c0 + i];
    }
    __syncthreads();

    uint32_t qf[4][4];
    {
        uint32_t base = cvta_smem(sQ);
#pragma unroll
        for (int kc = 0; kc < 4; kc++){
            uint32_t addr = base + (uint32_t)((warp*16 + (sel&1)*8 + l7) * (PADH*2))
                          + (uint32_t)((sel>>1)*16 + kc*32);
            ldm4(qf[kc], addr);
        }
    }

    auto issue_kv = [&](int t, int buf){
        int row = tid >> 1, c0 = (tid & 1) * 4;
        const __half* kg = Kg + (size_t)(t*64 + row) * DM3;
        const __half* vg = Vg + (size_t)(t*64 + row) * DM3;
        uint32_t kb = cvta_smem(sK[buf]) + row * (PADH*2);
        uint32_t vb = cvta_smem(sV[buf]) + row * (PADH*2);
#pragma unroll
        for (int i = 0; i < 4; i++){
            cpa16(kb + (c0+i)*16, kg + (c0+i)*8);
            cpa16(vb + (c0+i)*16, vg + (c0+i)*8);
        }
        cp_commit();
    };

    float m0 = -1e30f, m1 = -1e30f, l0 = 0.f, l1 = 0.f;
    float oacc[8][4];
#pragma unroll
    for (int nb = 0; nb < 8; nb++)
#pragma unroll
        for (int i = 0; i < 4; i++) oacc[nb][i] = 0.f;

    const int nt = qb + 1;
    issue_kv(0, 0);

    for (int t = 0; t < nt; t++){
        if (t + 1 < nt){ issue_kv(t + 1, (t + 1) & 1); cp_wait1(); }
        else cp_wait0();
        __syncthreads();
        const int buf = t & 1;

        float sc[8][4];
#pragma unroll
        for (int nb = 0; nb < 8; nb++)
#pragma unroll
            for (int i = 0; i < 4; i++) sc[nb][i] = 0.f;

        uint32_t kbase = cvta_smem(sK[buf]);
#pragma unroll
        for (int kc = 0; kc < 4; kc++){
            uint32_t kf[16];
#pragma unroll
            for (int nb16 = 0; nb16 < 4; nb16++){
                uint32_t addr = kbase + (uint32_t)((nb16*16 + (sel>>1)*8 + l7) * (PADH*2))
                              + (uint32_t)((sel&1)*16 + kc*32);
                ldm4(&kf[nb16*4], addr);
            }
#pragma unroll
            for (int nb16 = 0; nb16 < 4; nb16++){
                mma_f16(sc[2*nb16],   qf[kc], &kf[nb16*4]);
                mma_f16(sc[2*nb16+1], qf[kc], &kf[nb16*4 + 2]);
            }
        }

#pragma unroll
        for (int nb = 0; nb < 8; nb++)
#pragma unroll
            for (int i = 0; i < 4; i++) sc[nb][i] *= 0.125f;
        if (t == qb){
            int row0 = warp*16 + g, row1 = row0 + 8;
#pragma unroll
            for (int nb = 0; nb < 8; nb++){
                int cb = nb*8 + 2*tig;
                if (cb     > row0) sc[nb][0] = -1e30f;
                if (cb + 1 > row0) sc[nb][1] = -1e30f;
                if (cb     > row1) sc[nb][2] = -1e30f;
                if (cb + 1 > row1) sc[nb][3] = -1e30f;
            }
        }

        float tm0 = -1e30f, tm1 = -1e30f;
#pragma unroll
        for (int nb = 0; nb < 8; nb++){
            tm0 = fmaxf(tm0, fmaxf(sc[nb][0], sc[nb][1]));
            tm1 = fmaxf(tm1, fmaxf(sc[nb][2], sc[nb][3]));
        }
        tm0 = fmaxf(tm0, __shfl_xor_sync(0xffffffffu, tm0, 1));
        tm0 = fmaxf(tm0, __shfl_xor_sync(0xffffffffu, tm0, 2));
        tm1 = fmaxf(tm1, __shfl_xor_sync(0xffffffffu, tm1, 1));
        tm1 = fmaxf(tm1, __shfl_xor_sync(0xffffffffu, tm1, 2));

        float nm0 = fmaxf(m0, tm0), nm1 = fmaxf(m1, tm1);
        float cf0 = __expf(m0 - nm0), cf1 = __expf(m1 - nm1);
        l0 *= cf0; l1 *= cf1;
#pragma unroll
        for (int nb = 0; nb < 8; nb++){
            oacc[nb][0] *= cf0; oacc[nb][1] *= cf0;
            oacc[nb][2] *= cf1; oacc[nb][3] *= cf1;
        }
        float rs0 = 0.f, rs1 = 0.f;
#pragma unroll
        for (int nb = 0; nb < 8; nb++){
            sc[nb][0] = __expf(sc[nb][0] - nm0);
            sc[nb][1] = __expf(sc[nb][1] - nm0);
            sc[nb][2] = __expf(sc[nb][2] - nm1);
            sc[nb][3] = __expf(sc[nb][3] - nm1);
            rs0 += sc[nb][0] + sc[nb][1];
            rs1 += sc[nb][2] + sc[nb][3];
        }
        rs0 += __shfl_xor_sync(0xffffffffu, rs0, 1);
        rs0 += __shfl_xor_sync(0xffffffffu, rs0, 2);
        rs1 += __shfl_xor_sync(0xffffffffu, rs1, 1);
        rs1 += __shfl_xor_sync(0xffffffffu, rs1, 2);
        l0 += rs0; l1 += rs1; m0 = nm0; m1 = nm1;

        uint32_t vbase = cvta_smem(sV[buf]);
#pragma unroll
        for (int kc = 0; kc < 4; kc++){
            uint32_t pa[4];
            pa[0] = h2pk(sc[2*kc][0],   sc[2*kc][1]);
            pa[1] = h2pk(sc[2*kc][2],   sc[2*kc][3]);
            pa[2] = h2pk(sc[2*kc+1][0], sc[2*kc+1][1]);
            pa[3] = h2pk(sc[2*kc+1][2], sc[2*kc+1][3]);
            uint32_t vf[16];
#pragma unroll
            for (int db = 0; db < 4; db++){
                uint32_t addr = vbase + (uint32_t)((kc*16 + (sel&1)*8 + l7) * (PADH*2))
                              + (uint32_t)(db*32 + (sel>>1)*16);
                ldm4t(&vf[db*4], addr);
            }
#pragma unroll
            for (int db = 0; db < 4; db++){
                mma_f16(oacc[2*db],   pa, &vf[db*4]);
                mma_f16(oacc[2*db+1], pa, &vf[db*4 + 2]);
            }
        }
        __syncthreads();
    }

    float inv0 = 1.f / l0, inv1 = 1.f / l1;
    int row0 = n*SEQ + qb*64 + warp*16 + g;
#pragma unroll
    for (int nb = 0; nb < 8; nb++){
        int col = h*HDIM + nb*8 + 2*tig;
        *(uint32_t*)&o[(size_t)row0 * DM + col] =
            h2pk(oacc[nb][0]*inv0, oacc[nb][1]*inv0);
        *(uint32_t*)&o[(size_t)(row0 + 8) * DM + col] =
            h2pk(oacc[nb][2]*inv1, oacc[nb][3]*inv1);
    }
}

// ---- residual + LayerNorm (single pass over o via registers) ----------------
__global__ void __launch_bounds__(256)
ln_residual(float* __restrict__ x, const float* __restrict__ o,
            const float* __restrict__ g, const float* __restrict__ b,
            __half* __restrict__ hx)
{
    __shared__ float red[256];
    __shared__ float s_mean, s_rstd;
    int row = blockIdx.x;
    int tid = threadIdx.x;
    const float4* o4 = (const float4*)(o + (size_t)row * DM);
    float4*       x4 = (float4*)(x + (size_t)row * DM);
    __half*      hrow = hx + (size_t)row * DM;

    float4 ov = o4[tid];
    float s = ov.x + ov.y + ov.z + ov.w;
    red[tid] = s; __syncthreads();
    for (int off = 128; off > 0; off >>= 1) {
        if (tid < off) red[tid] += red[tid + off];
        __syncthreads();
    }
    if (tid == 0) s_mean = red[0] * (1.f / DM);
    __syncthreads();
    float mean = s_mean;

    float dx = ov.x - mean, dy = ov.y - mean, dz = ov.z - mean, dw = ov.w - mean;
    red[tid] = dx*dx + dy*dy + dz*dz + dw*dw; __syncthreads();
    for (int off = 128; off > 0; off >>= 1) {
        if (tid < off) red[tid] += red[tid + off];
        __syncthreads();
    }
    if (tid == 0) s_rstd = rsqrtf(red[0] * (1.f / DM) + 1e-5f);
    __syncthreads();
    float rstd = s_rstd;

    const float4 gv = ((const float4*)g)[tid];
    const float4 bv = ((const float4*)b)[tid];
    float4 xv = x4[tid];
    xv.x += dx * rstd * gv.x + bv.x;
    xv.y += dy * rstd * gv.y + bv.y;
    xv.z += dz * rstd * gv.z + bv.z;
    xv.w += dw * rstd * gv.w + bv.w;
    x4[tid] = xv;
    uint2 hh = make_uint2(h2pk(xv.x, xv.y), h2pk(xv.z, xv.w));
    *(uint2*)(hrow + tid * 4) = hh;
}

// ---------------- launch ----------------------------------------------------
extern "C" void kernel_launch(void* const* d_in, const int* in_sizes, int n_in,
                              void* d_out, int out_size)
{
    const int*   tokens = (const int*)  d_in[0];
    const float* emb    = (const float*)d_in[1];
    const float* pe     = (const float*)d_in[2];
    const float* Wq     = (const float*)d_in[3];
    const float* bq     = (const float*)d_in[4];
    const float* Wk     = (const float*)d_in[5];
    const float* bk     = (const float*)d_in[6];
    const float* Wv     = (const float*)d_in[7];
    const float* bv     = (const float*)d_in[8];
    const float* Wo     = (const float*)d_in[9];
    const float* bo     = (const float*)d_in[10];
    const float* g1     = (const float*)d_in[11];
    const float* be1    = (const float*)d_in[12];
    const float* W1     = (const float*)d_in[13];
    const float* b1     = (const float*)d_in[14];
    const float* W2     = (const float*)d_in[15];
    const float* b2     = (const float*)d_in[16];
    const float* g2     = (const float*)d_in[17];
    const float* be2    = (const float*)d_in[18];
    const float* Wfc    = (const float*)d_in[19];
    const float* bfc    = (const float*)d_in[20];
    float* out = (float*)d_out;

    float *x, *t0, *bqkv;
    __half *hWqkv, *hWo, *hW1, *hW2, *hWfc, *hx, *ht3, *hf1, *hqkv;
    cudaGetSymbolAddress((void**)&x,   g_x);
    cudaGetSymbolAddress((void**)&t0,  g_t0);
    cudaGetSymbolAddress((void**)&bqkv, g_bqkv);
    cudaGetSymbolAddress((void**)&hWqkv, g_hWqkv);
    cudaGetSymbolAddress((void**)&hWo, g_hWo);
    cudaGetSymbolAddress((void**)&hW1, g_hW1);
    cudaGetSymbolAddress((void**)&hW2, g_hW2);
    cudaGetSymbolAddress((void**)&hWfc, g_hWfc);
    cudaGetSymbolAddress((void**)&hx,  g_hx);
    cudaGetSymbolAddress((void**)&ht3, g_ht3);
    cudaGetSymbolAddress((void**)&hf1, g_hf1);
    cudaGetSymbolAddress((void**)&hqkv, g_hqkv);

    cudaFuncSetAttribute(hgemm<false,false,4>,
                         cudaFuncAttributeMaxDynamicSharedMemorySize, GEMM_SMEM_4);
    cudaFuncSetAttribute(hgemm<false,true,4>,
                         cudaFuncAttributeMaxDynamicSharedMemorySize, GEMM_SMEM_4);
    cudaFuncSetAttribute(hgemm<true,true,4>,
                         cudaFuncAttributeMaxDynamicSharedMemorySize, GEMM_SMEM_4);
    cudaFuncSetAttribute(hgemm<false,false,2>,
                         cudaFuncAttributeMaxDynamicSharedMemorySize, GEMM_SMEM_2);

    const int CB = 256;
    pack_qkv_w<<<(int)(((long long)NL*DM*DM3/4 + CB-1)/CB), CB>>>(Wq, Wk, Wv, hWqkv);
    pack_qkv_b<<<(NL*DM3 + CB-1)/CB, CB>>>(bq, bk, bv, bqkv);
    cvt_f2h<<<(NL*DM*DM/4 + CB-1)/CB, CB>>>(Wo, hWo, NL*DM*DM);
    cvt_f2h<<<(NL*DM*DFF/4 + CB-1)/CB, CB>>>(W1, hW1, NL*DM*DFF);
    cvt_f2h<<<(NL*DFF*DM/4 + CB-1)/CB, CB>>>(W2, hW2, NL*DFF*DM);
    cvt_f2h<<<(DM*VOCAB/4 + CB-1)/CB, CB>>>(Wfc, hWfc, DM*VOCAB);

    embed_kernel<<<(MROWS * DM + 255) / 256, 256>>>(tokens, emb, pe, x, hx);

    dim3 gQKV(MROWS / 128, DM3 / 128);  // (16, 24)
    dim3 gDD64(MROWS / 64, DM / 128);   // (32, 8) = 256 CTAs
    dim3 gDF(MROWS / 128, DFF / 128);   // (16, 32)
    dim3 gAttn(SEQ / 64, NH, BATCH);    // (8, 16, 4)

    for (int l = 0; l < NL; l++) {
        const __half* wqkv = hWqkv + (size_t)l * DM * DM3;
        const __half* wo = hWo + (size_t)l * DM * DM;
        const __half* w1 = hW1 + (size_t)l * DM * DFF;
        const __half* w2 = hW2 + (size_t)l * DFF * DM;

        hgemm<false,true,4><<<gQKV, 256, GEMM_SMEM_4>>>(hx, wqkv, bqkv + l * DM3, hqkv, DM3, DM);

        fattn<<<gAttn, 128>>>(hqkv, ht3);

        hgemm<false,false,2><<<gDD64, 256, GEMM_SMEM_2>>>(ht3, wo, bo + l * DM, t0, DM, DM);
        ln_residual<<<MROWS, 256>>>(x, t0, g1 + l * DM, be1 + l * DM, hx);

        hgemm<true,true,4><<<gDF, 256, GEMM_SMEM_4>>>(hx, w1, b1 + l * DFF, hf1, DFF, DM);
        hgemm<false,false,2><<<gDD64, 256, GEMM_SMEM_2>>>(hf1, w2, b2 + l * DM, t0, DM, DFF);
        ln_residual<<<MROWS, 256>>>(x, t0, g2 + l * DM, be2 + l * DM, hx);
    }

    dim3 gV(MROWS / 128, VOCAB / 128);  // (16, 250)
    hgemm<false,false,4><<<gV, 256, GEMM_SMEM_4>>>(hx, hWfc, bfc, out, VOCAB, DM);
}